// round 11
// baseline (speedup 1.0000x reference)
#include <cuda_runtime.h>
#include <math.h>
#include <stdint.h>

#define BQ 4
#define TQ 8192
#define DQ 1024
#define CQ 64
#define NCQ 128
#define MQ (BQ*TQ)

// Scratch (static device arrays; no allocation allowed)
__device__ float g_v[(size_t)BQ * TQ * DQ];
__device__ float g_reads[(size_t)BQ * TQ * DQ];   // intra part
__device__ float g_p0[(size_t)BQ * TQ * DQ];      // inter partial, e-slice 0
__device__ float g_p1[(size_t)BQ * TQ * DQ];      // inter partial, e-slice 1

__device__ __forceinline__ float sigmoidf_(float x) { return 1.0f / (1.0f + expf(-x)); }
__device__ __forceinline__ uint32_t fu(float x) { return __float_as_uint(x); }
__device__ __forceinline__ float f2tf_f(float x) {
    uint32_t r;
    asm("cvt.rna.tf32.f32 %0, %1;" : "=r"(r) : "f"(x));
    return __uint_as_float(r);
}
// D += A*B, tf32 m16n8k8
__device__ __forceinline__ void mma8(float* d, const uint32_t* a, const uint32_t* b) {
    asm volatile(
        "mma.sync.aligned.m16n8k8.row.col.f32.tf32.tf32.f32 "
        "{%0,%1,%2,%3}, {%4,%5,%6,%7}, {%8,%9}, {%0,%1,%2,%3};\n"
        : "+f"(d[0]), "+f"(d[1]), "+f"(d[2]), "+f"(d[3])
        : "r"(a[0]), "r"(a[1]), "r"(a[2]), "r"(a[3]), "r"(b[0]), "r"(b[1]));
}

// ---------------------------------------------------------------------------
// tf32 GEMM: C = R + alpha*((A+A2+A3) @ B^T)   (A2/A3/R optional)
// A: M x 1024, B: 1024 x 1024, row-major K-contiguous. M = 32768.
// Block tile 128m x 256n, BK=16 double-buffered. 8 warps, warp tile 64x64.
// Smem holds operands in FRAGMENT order so inner loop uses LDS.128/LDS.64.
// ---------------------------------------------------------------------------
__global__ void __launch_bounds__(256) gemm_tf32(
    const float* __restrict__ A, const float* __restrict__ Bm,
    const float* __restrict__ A2, const float* __restrict__ A3,
    const float* __restrict__ R, float* __restrict__ C,
    const float* __restrict__ log_alpha_ptr)
{
    __shared__ float Af[2][2048];   // 2 ksec * 8 mt * 32 lane * 4 j
    __shared__ float Bf[2][4096];   // 2 ksec * 32 nt * 32 lane * 2 j

    const int tid = threadIdx.x, lane = tid & 31, wid = tid >> 5;
    const int g = lane >> 2, tg = lane & 3;
    const int wm = wid >> 2;        // 0..1  (64 m rows each)
    const int wn = wid & 3;         // 0..3  (64 n cols each)
    const int m0 = blockIdx.y * 128, n0 = blockIdx.x * 256;

    // A staging coords: row lr (0..127), k offset lk (0 or 8)
    const int lrA = tid >> 1, lkA = (tid & 1) * 8;
    const int ktA = lkA >> 3, mtA = lrA >> 4, jmA = (lrA & 8) >> 3;
    const int baseA = ((ktA * 8 + mtA) * 32 + (lrA & 7) * 4) * 4 + jmA * 2;
    // B staging coords: row n = tid (0..255), all 16 k
    const int ntB = tid >> 3;
    const int baseB0 = ((0 * 32 + ntB) * 32 + (tid & 7) * 4) * 2;
    const int baseB1 = ((1 * 32 + ntB) * 32 + (tid & 7) * 4) * 2;

    const float* Ap  = A  + (size_t)(m0 + lrA) * DQ + lkA;
    const float* Ap2 = A2 ? A2 + (size_t)(m0 + lrA) * DQ + lkA : nullptr;
    const float* Ap3 = A3 ? A3 + (size_t)(m0 + lrA) * DQ + lkA : nullptr;
    const float* Bp  = Bm + (size_t)(n0 + tid) * DQ;

    float av[8];
    float bvv[16];

    // --- prologue: load kt=0 and stage into buf 0 ---
    {
        float4 x0 = *(const float4*)Ap, x1 = *(const float4*)(Ap + 4);
        av[0]=x0.x; av[1]=x0.y; av[2]=x0.z; av[3]=x0.w; av[4]=x1.x; av[5]=x1.y; av[6]=x1.z; av[7]=x1.w;
        if (Ap2) { float4 y0=*(const float4*)Ap2, y1=*(const float4*)(Ap2+4);
            av[0]+=y0.x; av[1]+=y0.y; av[2]+=y0.z; av[3]+=y0.w; av[4]+=y1.x; av[5]+=y1.y; av[6]+=y1.z; av[7]+=y1.w; }
        if (Ap3) { float4 y0=*(const float4*)Ap3, y1=*(const float4*)(Ap3+4);
            av[0]+=y0.x; av[1]+=y0.y; av[2]+=y0.z; av[3]+=y0.w; av[4]+=y1.x; av[5]+=y1.y; av[6]+=y1.z; av[7]+=y1.w; }
        #pragma unroll
        for (int q = 0; q < 4; q++) {
            float4 z = *(const float4*)(Bp + q * 4);
            bvv[q*4+0]=z.x; bvv[q*4+1]=z.y; bvv[q*4+2]=z.z; bvv[q*4+3]=z.w;
        }
        #pragma unroll
        for (int c = 0; c < 4; c++) {
            *(float2*)&Af[0][baseA + c * 4]  = make_float2(f2tf_f(av[c]),      f2tf_f(av[4 + c]));
            *(float2*)&Bf[0][baseB0 + c * 2] = make_float2(f2tf_f(bvv[c]),     f2tf_f(bvv[4 + c]));
            *(float2*)&Bf[0][baseB1 + c * 2] = make_float2(f2tf_f(bvv[8 + c]), f2tf_f(bvv[12 + c]));
        }
    }
    __syncthreads();

    float acc[4][8][4];
    #pragma unroll
    for (int i = 0; i < 4; i++) for (int j = 0; j < 8; j++) for (int q = 0; q < 4; q++) acc[i][j][q] = 0.f;

    const int nK = DQ / 16;  // 64
    int buf = 0;
    for (int kt = 0; kt < nK; kt++) {
        // prefetch next tile into registers
        if (kt < nK - 1) {
            const size_t off = (size_t)(kt + 1) * 16;
            float4 x0 = *(const float4*)(Ap + off), x1 = *(const float4*)(Ap + off + 4);
            av[0]=x0.x; av[1]=x0.y; av[2]=x0.z; av[3]=x0.w; av[4]=x1.x; av[5]=x1.y; av[6]=x1.z; av[7]=x1.w;
            if (Ap2) { float4 y0=*(const float4*)(Ap2+off), y1=*(const float4*)(Ap2+off+4);
                av[0]+=y0.x; av[1]+=y0.y; av[2]+=y0.z; av[3]+=y0.w; av[4]+=y1.x; av[5]+=y1.y; av[6]+=y1.z; av[7]+=y1.w; }
            if (Ap3) { float4 y0=*(const float4*)(Ap3+off), y1=*(const float4*)(Ap3+off+4);
                av[0]+=y0.x; av[1]+=y0.y; av[2]+=y0.z; av[3]+=y0.w; av[4]+=y1.x; av[5]+=y1.y; av[6]+=y1.z; av[7]+=y1.w; }
            #pragma unroll
            for (int q = 0; q < 4; q++) {
                float4 z = *(const float4*)(Bp + off + q * 4);
                bvv[q*4+0]=z.x; bvv[q*4+1]=z.y; bvv[q*4+2]=z.z; bvv[q*4+3]=z.w;
            }
        }
        // compute on current buffer
        #pragma unroll
        for (int s = 0; s < 2; s++) {
            uint32_t a[4][4], bb[8][2];
            #pragma unroll
            for (int mi = 0; mi < 4; mi++) {
                float4 f = *(const float4*)&Af[buf][((s * 8 + wm * 4 + mi) * 32 + lane) * 4];
                a[mi][0] = fu(f.x); a[mi][1] = fu(f.z); a[mi][2] = fu(f.y); a[mi][3] = fu(f.w);
            }
            #pragma unroll
            for (int ni = 0; ni < 8; ni++) {
                float2 f = *(const float2*)&Bf[buf][((s * 32 + wn * 8 + ni) * 32 + lane) * 2];
                bb[ni][0] = fu(f.x); bb[ni][1] = fu(f.y);
            }
            #pragma unroll
            for (int mi = 0; mi < 4; mi++)
                #pragma unroll
                for (int ni = 0; ni < 8; ni++)
                    mma8(acc[mi][ni], a[mi], bb[ni]);
        }
        // stage prefetched tile into other buffer
        if (kt < nK - 1) {
            const int nb = buf ^ 1;
            #pragma unroll
            for (int c = 0; c < 4; c++) {
                *(float2*)&Af[nb][baseA + c * 4]  = make_float2(f2tf_f(av[c]),      f2tf_f(av[4 + c]));
                *(float2*)&Bf[nb][baseB0 + c * 2] = make_float2(f2tf_f(bvv[c]),     f2tf_f(bvv[4 + c]));
                *(float2*)&Bf[nb][baseB1 + c * 2] = make_float2(f2tf_f(bvv[8 + c]), f2tf_f(bvv[12 + c]));
            }
            __syncthreads();
            buf = nb;
        }
    }

    const bool useR = (R != nullptr);
    float alpha = 1.0f;
    if (useR) alpha = expf(*log_alpha_ptr);

    #pragma unroll
    for (int mi = 0; mi < 4; mi++) {
        #pragma unroll
        for (int ni = 0; ni < 8; ni++) {
            const int row0 = m0 + wm * 64 + mi * 16 + g;
            const int col  = n0 + wn * 64 + ni * 8 + 2 * tg;
            float2 v0 = make_float2(acc[mi][ni][0], acc[mi][ni][1]);
            float2 v1 = make_float2(acc[mi][ni][2], acc[mi][ni][3]);
            if (useR) {
                float2 r0 = *(const float2*)&R[(size_t)row0 * DQ + col];
                float2 r1 = *(const float2*)&R[(size_t)(row0 + 8) * DQ + col];
                v0.x = fmaf(alpha, v0.x, r0.x); v0.y = fmaf(alpha, v0.y, r0.y);
                v1.x = fmaf(alpha, v1.x, r1.x); v1.y = fmaf(alpha, v1.y, r1.y);
            }
            *(float2*)&C[(size_t)row0 * DQ + col]       = v0;
            *(float2*)&C[(size_t)(row0 + 8) * DQ + col] = v1;
        }
    }
}

// ---------------------------------------------------------------------------
// Intra-chunk kernel (parallel over all (b,chunk)), fp32.
// ---------------------------------------------------------------------------
__global__ void __launch_bounds__(256) intra_kernel(
    const float* __restrict__ out, const float* __restrict__ decay_ptr)
{
    const int j = blockIdx.x, b = blockIdx.y;
    const float gamma = sigmoidf_(*decay_ptr);
    const float lg = logf(gamma);
    const int tid = threadIdx.x, tx = tid & 15, ty = tid >> 4;
    const int lr = tid >> 2, lk = (tid & 3) << 2;

    __shared__ float SA[16][64];
    __shared__ float SB[16][64];
    __shared__ float Ps[64][64];
    __shared__ float Vs[64][64];

    const float* rbase = out + ((size_t)b * TQ + (size_t)j * CQ) * DQ;
    const int wrow = j * CQ + lr - 1;
    const bool wvalid = (wrow >= 0);
    const float* wptr = out + ((size_t)b * TQ + (size_t)(wvalid ? wrow : 0)) * DQ;

    float acc[4][4];
    #pragma unroll
    for (int i = 0; i < 4; i++) for (int jj = 0; jj < 4; jj++) acc[i][jj] = 0.0f;

    for (int kt = 0; kt < 64; kt++) {
        __syncthreads();
        float4 ra = *(const float4*)(rbase + (size_t)lr * DQ + kt * 16 + lk);
        float4 wa = make_float4(0.f, 0.f, 0.f, 0.f);
        if (wvalid) wa = *(const float4*)(wptr + kt * 16 + lk);
        SA[lk+0][lr] = ra.x; SA[lk+1][lr] = ra.y; SA[lk+2][lr] = ra.z; SA[lk+3][lr] = ra.w;
        SB[lk+0][lr] = wa.x; SB[lk+1][lr] = wa.y; SB[lk+2][lr] = wa.z; SB[lk+3][lr] = wa.w;
        __syncthreads();
        #pragma unroll
        for (int kk = 0; kk < 16; kk++) {
            float af[4], bf[4];
            *(float4*)af = *(const float4*)&SA[kk][ty * 4];
            *(float4*)bf = *(const float4*)&SB[kk][tx * 4];
            #pragma unroll
            for (int i = 0; i < 4; i++)
                #pragma unroll
                for (int jj = 0; jj < 4; jj++)
                    acc[i][jj] = fmaf(af[i], bf[jj], acc[i][jj]);
        }
    }
    __syncthreads();
    #pragma unroll
    for (int i = 0; i < 4; i++)
        #pragma unroll
        for (int jj = 0; jj < 4; jj++) {
            const int c = ty * 4 + i, e = tx * 4 + jj;
            const float msk = (c > e) ? expf(lg * (float)(c - 1 - e)) : 0.0f;
            Ps[c][e] = acc[i][jj] * msk;
        }

    const float* vbase = g_v + ((size_t)b * TQ + (size_t)j * CQ) * DQ;
    float* rd = g_reads + ((size_t)b * TQ + (size_t)j * CQ) * DQ;
    for (int dt = 0; dt < 16; dt++) {
        __syncthreads();
        #pragma unroll
        for (int p = 0; p < 4; p++) {
            const int er = p * 16 + ty;
            *(float4*)&Vs[er][tx * 4] = *(const float4*)(vbase + (size_t)er * DQ + dt * 64 + tx * 4);
        }
        __syncthreads();
        float a2[4][4];
        #pragma unroll
        for (int i = 0; i < 4; i++) for (int jj = 0; jj < 4; jj++) a2[i][jj] = 0.0f;
        #pragma unroll 16
        for (int e = 0; e < 64; e++) {
            float pf[4], vf[4];
            pf[0] = Ps[ty*4+0][e]; pf[1] = Ps[ty*4+1][e]; pf[2] = Ps[ty*4+2][e]; pf[3] = Ps[ty*4+3][e];
            *(float4*)vf = *(const float4*)&Vs[e][tx * 4];
            #pragma unroll
            for (int i = 0; i < 4; i++)
                #pragma unroll
                for (int jj = 0; jj < 4; jj++)
                    a2[i][jj] = fmaf(pf[i], vf[jj], a2[i][jj]);
        }
        #pragma unroll
        for (int i = 0; i < 4; i++) {
            float4 o; o.x = a2[i][0]; o.y = a2[i][1]; o.z = a2[i][2]; o.w = a2[i][3];
            *(float4*)&rd[(size_t)(ty * 4 + i) * DQ + dt * 64 + tx * 4] = o;
        }
    }
}

// ---------------------------------------------------------------------------
// Fused scan kernel (256 threads) with:
//  - sec1 rs tile prefetched into registers at chunk start
//  - chunk-invariant expf hoisted
//  - NEW: p1 and p2 inner loops software-pipelined (operands for iteration
//    k+1 loaded from smem while mma for iteration k executes)
// Grid (16 d-tiles, 2 e-slices, 4 batch) = 128 CTAs.
// ---------------------------------------------------------------------------
#define WS_STRIDE 516
#define RS_STRIDE 260
#define US_STRIDE 68
#define SCAN_WORDS (64*WS_STRIDE + 64*RS_STRIDE + 64*US_STRIDE + 520)
#define SCAN_SMEM (SCAN_WORDS * 4)

__global__ void __launch_bounds__(256) scan_kernel(
    const float* __restrict__ out, const float* __restrict__ decay_ptr,
    float* __restrict__ p0, float* __restrict__ p1)
{
    extern __shared__ float sm[];
    float* Ws = sm;                                  // [64][516]
    float* rs = Ws + 64 * WS_STRIDE;                 // [64][260]
    float* us = rs + 64 * RS_STRIDE;                 // [64][68]
    float* prevrow = us + 64 * US_STRIDE;            // [520] (512 payload)

    const int dt = blockIdx.x, es = blockIdx.y, b = blockIdx.z;
    const int d0g = dt * 64;
    const int e0g = es * 512;
    float* pout = (es == 0) ? p0 : p1;

    const int tid = threadIdx.x, lane = tid & 31, wid = tid >> 5;
    const int g = lane >> 2, tg = lane & 3;
    const float gamma = sigmoidf_(*decay_ptr);
    const float lg = logf(gamma);
    const float gC = expf(lg * 64.0f);

    for (int i = tid; i < SCAN_WORDS; i += 256) sm[i] = 0.0f;

    const float* outb = out + (size_t)b * TQ * DQ;
    const float* vb   = g_v + (size_t)b * TQ * DQ;
    float* pb = pout + (size_t)b * TQ * DQ;

    // p1 warp partition: 4 warps over c (m), 2 groups over d (4 n-tiles each)
    const int wm  = (wid & 3) * 16;
    const int wn4 = (wid >> 2) * 4;

    // hoisted per-thread constants (chunk-invariant)
    float gw_it[4];
    #pragma unroll
    for (int it = 0; it < 4; it++) {
        const int c = (tid + it * 256) >> 4;
        gw_it[it] = expf(lg * (float)(63 - c));
    }
    const float s0 = expf(lg * (float)(wm + g));
    const float s1 = expf(lg * (float)(wm + g + 8));

    for (int t = 0; t < NCQ; t++) {
        // ---- stage us[c][d] = v[c,d]*gamma^(63-c), prevrow, rs(sec0); prefetch rs(sec1) ----
        #pragma unroll
        for (int it = 0; it < 4; it++) {
            const int i = tid + it * 256;
            const int c = i >> 4, x = (i & 15) << 2;
            float4 vv = *(const float4*)(vb + (size_t)(t * 64 + c) * DQ + d0g + x);
            float* dst = us + c * US_STRIDE + x;
            const float gw = gw_it[it];
            dst[0] = f2tf_f(vv.x * gw); dst[1] = f2tf_f(vv.y * gw);
            dst[2] = f2tf_f(vv.z * gw); dst[3] = f2tf_f(vv.w * gw);
        }
        {
            const int e2 = tid * 2;
            float2 pr = make_float2(0.f, 0.f);
            if (t > 0) pr = *(const float2*)(outb + (size_t)(t * 64 - 1) * DQ + e0g + e2);
            prevrow[e2]     = f2tf_f(pr.x);
            prevrow[e2 + 1] = f2tf_f(pr.y);
        }
        #pragma unroll
        for (int it = 0; it < 16; it++) {
            const int i = tid + it * 256;
            const int c = i >> 6, x = (i & 63) << 2;
            float4 rv = *(const float4*)(outb + (size_t)(t * 64 + c) * DQ + e0g + x);
            float* dst = rs + c * RS_STRIDE + x;
            dst[0] = f2tf_f(rv.x); dst[1] = f2tf_f(rv.y);
            dst[2] = f2tf_f(rv.z); dst[3] = f2tf_f(rv.w);
        }
        float4 r1v[16];
        #pragma unroll
        for (int it = 0; it < 16; it++) {
            const int i = tid + it * 256;
            const int c = i >> 6, x = (i & 63) << 2;
            r1v[it] = *(const float4*)(outb + (size_t)(t * 64 + c) * DQ + e0g + 256 + x);
        }

        float acc1[4][4];
        #pragma unroll
        for (int n = 0; n < 4; n++) for (int q = 0; q < 4; q++) acc1[n][q] = 0.f;

        #pragma unroll
        for (int sec = 0; sec < 2; sec++) {
            if (sec == 1) {
                // store prefetched rs(sec1) from registers (no LDG latency here)
                #pragma unroll
                for (int it = 0; it < 16; it++) {
                    const int i = tid + it * 256;
                    const int c = i >> 6, x = (i & 63) << 2;
                    float* dst = rs + c * RS_STRIDE + x;
                    dst[0] = f2tf_f(r1v[it].x); dst[1] = f2tf_f(r1v[it].y);
                    dst[2] = f2tf_f(r1v[it].z); dst[3] = f2tf_f(r1v[it].w);
                }
            }
            __syncthreads();

            // ---- phase 1 (pipelined): acc1 += r(sec) @ Ws(sec)^T  (m=c,n=d,k=e) ----
            if (t > 0) {
                const float* wsec = Ws + sec * 256;
                uint32_t aC[4], bC[4][2];
                // prologue: k = 0
                aC[0] = fu(rs[(wm + g    ) * RS_STRIDE + tg    ]);
                aC[1] = fu(rs[(wm + g + 8) * RS_STRIDE + tg    ]);
                aC[2] = fu(rs[(wm + g    ) * RS_STRIDE + tg + 4]);
                aC[3] = fu(rs[(wm + g + 8) * RS_STRIDE + tg + 4]);
                #pragma unroll
                for (int n = 0; n < 4; n++) {
                    const int d = (wn4 + n) * 8 + g;
                    bC[n][0] = fu(wsec[d * WS_STRIDE + tg    ]);
                    bC[n][1] = fu(wsec[d * WS_STRIDE + tg + 4]);
                }
                #pragma unroll 4
                for (int k = 0; k < 32; k++) {
                    uint32_t aN[4], bN[4][2];
                    if (k < 31) {
                        const int ko = (k + 1) * 8;
                        aN[0] = fu(rs[(wm + g    ) * RS_STRIDE + ko + tg    ]);
                        aN[1] = fu(rs[(wm + g + 8) * RS_STRIDE + ko + tg    ]);
                        aN[2] = fu(rs[(wm + g    ) * RS_STRIDE + ko + tg + 4]);
                        aN[3] = fu(rs[(wm + g + 8) * RS_STRIDE + ko + tg + 4]);
                        #pragma unroll
                        for (int n = 0; n < 4; n++) {
                            const int d = (wn4 + n) * 8 + g;
                            bN[n][0] = fu(wsec[d * WS_STRIDE + ko + tg    ]);
                            bN[n][1] = fu(wsec[d * WS_STRIDE + ko + tg + 4]);
                        }
                    }
                    #pragma unroll
                    for (int n = 0; n < 4; n++)
                        mma8(acc1[n], aC, bC[n]);
                    if (k < 31) {
                        #pragma unroll
                        for (int q = 0; q < 4; q++) aC[q] = aN[q];
                        #pragma unroll
                        for (int n = 0; n < 4; n++) { bC[n][0] = bN[n][0]; bC[n][1] = bN[n][1]; }
                    }
                }
            }

            // ---- phase 2 (pipelined): acc2 = w(sec)^T @ u  (m=e,n=d,k=c) ----
            float acc2[2][8][4];
            #pragma unroll
            for (int m = 0; m < 2; m++) for (int n = 0; n < 8; n++) for (int q = 0; q < 4; q++) acc2[m][n][q] = 0.f;
            const float* prsec = prevrow + sec * 256;
            {
                uint32_t aC[2][4], bC[8][2];
                // prologue: kk = 0  (c0 = tg-1 may hit prevrow)
                {
                    const int c0 = tg - 1, c1 = tg + 3;
                    const float* r0 = (c0 >= 0) ? (rs + c0 * RS_STRIDE) : prsec;
                    const float* r1 = rs + c1 * RS_STRIDE;
                    #pragma unroll
                    for (int m = 0; m < 2; m++) {
                        const int e = (wid * 2 + m) * 16;
                        aC[m][0] = fu(r0[e + g    ]);
                        aC[m][1] = fu(r0[e + g + 8]);
                        aC[m][2] = fu(r1[e + g    ]);
                        aC[m][3] = fu(r1[e + g + 8]);
                    }
                    #pragma unroll
                    for (int n = 0; n < 8; n++) {
                        bC[n][0] = fu(us[(tg    ) * US_STRIDE + n * 8 + g]);
                        bC[n][1] = fu(us[(tg + 4) * US_STRIDE + n * 8 + g]);
                    }
                }
                #pragma unroll
                for (int kk = 0; kk < 8; kk++) {
                    uint32_t aN[2][4], bN[8][2];
                    if (kk < 7) {
                        const int c0 = (kk + 1) * 8 + tg - 1;   // >= 7, always in rs
                        const int c1 = (kk + 1) * 8 + tg + 3;
                        const float* r0 = rs + c0 * RS_STRIDE;
                        const float* r1 = rs + c1 * RS_STRIDE;
                        #pragma unroll
                        for (int m = 0; m < 2; m++) {
                            const int e = (wid * 2 + m) * 16;
                            aN[m][0] = fu(r0[e + g    ]);
                            aN[m][1] = fu(r0[e + g + 8]);
                            aN[m][2] = fu(r1[e + g    ]);
                            aN[m][3] = fu(r1[e + g + 8]);
                        }
                        #pragma unroll
                        for (int n = 0; n < 8; n++) {
                            bN[n][0] = fu(us[((kk + 1) * 8 + tg    ) * US_STRIDE + n * 8 + g]);
                            bN[n][1] = fu(us[((kk + 1) * 8 + tg + 4) * US_STRIDE + n * 8 + g]);
                        }
                    }
                    #pragma unroll
                    for (int m = 0; m < 2; m++)
                        #pragma unroll
                        for (int n = 0; n < 8; n++)
                            mma8(acc2[m][n], aC[m], bC[n]);
                    if (kk < 7) {
                        #pragma unroll
                        for (int m = 0; m < 2; m++)
                            #pragma unroll
                            for (int q = 0; q < 4; q++) aC[m][q] = aN[m][q];
                        #pragma unroll
                        for (int n = 0; n < 8; n++) { bC[n][0] = bN[n][0]; bC[n][1] = bN[n][1]; }
                    }
                }
            }
            __syncthreads();   // all p1 reads of Ws(sec) + all rs reads done

            // ---- RMW Ws(sec): W = gC*W + acc2 ; C frag is [m=e][n=d] ----
            #pragma unroll
            for (int m = 0; m < 2; m++) {
                const int e = sec * 256 + (wid * 2 + m) * 16;
                #pragma unroll
                for (int n = 0; n < 8; n++) {
                    const int d = n * 8 + 2 * tg;
                    float* w00 = &Ws[(size_t)d       * WS_STRIDE + e + g];
                    float* w01 = &Ws[(size_t)(d + 1) * WS_STRIDE + e + g];
                    float* w10 = &Ws[(size_t)d       * WS_STRIDE + e + g + 8];
                    float* w11 = &Ws[(size_t)(d + 1) * WS_STRIDE + e + g + 8];
                    *w00 = fmaf(gC, *w00, acc2[m][n][0]);
                    *w01 = fmaf(gC, *w01, acc2[m][n][1]);
                    *w10 = fmaf(gC, *w10, acc2[m][n][2]);
                    *w11 = fmaf(gC, *w11, acc2[m][n][3]);
                }
            }
        }

        // ---- store inter partial (gamma^c scaled), or zeros at t=0 ----
        if (t > 0) {
            const int c0 = wm + g, c1 = wm + g + 8;
            #pragma unroll
            for (int n = 0; n < 4; n++) {
                const int dg = d0g + (wn4 + n) * 8 + 2 * tg;
                float2 v0 = make_float2(acc1[n][0] * s0, acc1[n][1] * s0);
                float2 v1 = make_float2(acc1[n][2] * s1, acc1[n][3] * s1);
                *(float2*)(pb + (size_t)(t * 64 + c0) * DQ + dg) = v0;
                *(float2*)(pb + (size_t)(t * 64 + c1) * DQ + dg) = v1;
            }
        } else {
            #pragma unroll
            for (int it = 0; it < 4; it++) {
                const int i = tid + it * 256;
                const int c = i >> 4, x = (i & 15) << 2;
                *(float4*)(pb + (size_t)c * DQ + d0g + x) = make_float4(0.f, 0.f, 0.f, 0.f);
            }
        }
        __syncthreads();   // W RMW + staging buffers quiesced before next chunk
    }
}

// ---------------------------------------------------------------------------
extern "C" void kernel_launch(void* const* d_in, const int* in_sizes, int n_in,
                              void* d_out, int out_size)
{
    const float* out_in    = (const float*)d_in[0];
    const float* W_write   = (const float*)d_in[1];
    const float* W_read    = (const float*)d_in[2];
    const float* decay     = (const float*)d_in[3];
    const float* log_alpha = (const float*)d_in[4];
    float* outp = (float*)d_out;

    static bool attr_set = false;
    if (!attr_set) {
        cudaFuncSetAttribute(scan_kernel, cudaFuncAttributeMaxDynamicSharedMemorySize, SCAN_SMEM);
        attr_set = true;
    }

    void *pv = nullptr, *pr = nullptr, *pp0 = nullptr, *pp1 = nullptr;
    cudaGetSymbolAddress(&pv, g_v);
    cudaGetSymbolAddress(&pr, g_reads);
    cudaGetSymbolAddress(&pp0, g_p0);
    cudaGetSymbolAddress(&pp1, g_p1);

    dim3 ggemm(DQ / 256, MQ / 128);  // (4, 256)

    // 1) v = out @ W_write^T  (tf32)
    gemm_tf32<<<ggemm, 256>>>(out_in, W_write, nullptr, nullptr, nullptr, (float*)pv, nullptr);

    // 2) intra part of reads -> g_reads (parallel over chunks)
    intra_kernel<<<dim3(NCQ, BQ), 256>>>(out_in, decay);

    // 3) whole sequential scan in ONE kernel -> inter partials g_p0/g_p1
    scan_kernel<<<dim3(16, 2, BQ), 256, SCAN_SMEM>>>(out_in, decay, (float*)pp0, (float*)pp1);

    // 4) output = out + alpha * ((g_reads + g_p0 + g_p1) @ W_read^T)
    gemm_tf32<<<ggemm, 256>>>((const float*)pr, W_read, (const float*)pp0, (const float*)pp1,
                              out_in, outp, log_alpha);
}

// round 13
// speedup vs baseline: 1.1485x; 1.1485x over previous
#include <cuda_runtime.h>
#include <cuda_fp16.h>
#include <math.h>
#include <stdint.h>

#define BQ 4
#define TQ 8192
#define DQ 1024
#define CQ 64
#define NCQ 128
#define MQ (BQ*TQ)

// Scratch (static device arrays; no allocation allowed)
__device__ float g_v[(size_t)BQ * TQ * DQ];
__device__ float g_reads[(size_t)BQ * TQ * DQ];   // intra part
__device__ float g_p0[(size_t)BQ * TQ * DQ];      // inter partial, e-slice 0
__device__ float g_p1[(size_t)BQ * TQ * DQ];      // inter partial, e-slice 1

__device__ __forceinline__ float sigmoidf_(float x) { return 1.0f / (1.0f + expf(-x)); }
__device__ __forceinline__ uint32_t fu(float x) { return __float_as_uint(x); }
__device__ __forceinline__ float f2tf_f(float x) {
    uint32_t r;
    asm("cvt.rna.tf32.f32 %0, %1;" : "=r"(r) : "f"(x));
    return __uint_as_float(r);
}
__device__ __forceinline__ uint32_t pack_h2(float lo, float hi) {
    __half2 h = __floats2half2_rn(lo, hi);
    return *(uint32_t*)&h;
}
// tf32 mma (scan): D += A*B, m16n8k8
__device__ __forceinline__ void mma8(float* d, const uint32_t* a, const uint32_t* b) {
    asm volatile(
        "mma.sync.aligned.m16n8k8.row.col.f32.tf32.tf32.f32 "
        "{%0,%1,%2,%3}, {%4,%5,%6,%7}, {%8,%9}, {%0,%1,%2,%3};\n"
        : "+f"(d[0]), "+f"(d[1]), "+f"(d[2]), "+f"(d[3])
        : "r"(a[0]), "r"(a[1]), "r"(a[2]), "r"(a[3]), "r"(b[0]), "r"(b[1]));
}
// fp16 mma (GEMM): D += A*B, m16n8k16, f32 accumulate
__device__ __forceinline__ void mma16h(float* d, const uint32_t* a, const uint32_t* b) {
    asm volatile(
        "mma.sync.aligned.m16n8k16.row.col.f32.f16.f16.f32 "
        "{%0,%1,%2,%3}, {%4,%5,%6,%7}, {%8,%9}, {%0,%1,%2,%3};\n"
        : "+f"(d[0]), "+f"(d[1]), "+f"(d[2]), "+f"(d[3])
        : "r"(a[0]), "r"(a[1]), "r"(a[2]), "r"(a[3]), "r"(b[0]), "r"(b[1]));
}

// ---------------------------------------------------------------------------
// fp16 GEMM: C = R + alpha*((A+A2+A3) @ B^T)   (A2/A3/R optional)
// A: M x 1024, B: 1024 x 1024, row-major K-contiguous. M = 32768.
// Block 128m x 256n, BK=16 double-buffered, 8 warps, warp tile 64x64.
// Smem holds half2-packed operands in mma-fragment order:
//   A elem (m,k): Af[ (mt*32 + (m&7)*4 + ((k&7)>>1)) * 4 + (m&8)>>3 + 2*((k&8)>>3) ], half k&1
//   B elem (n,k): Bf[ (nt*32 + (n&7)*4 + ((k&7)>>1)) * 2 + ((k&8)>>3) ], half k&1
// Inner loop per warp per k16: 4x LDS.128 (A) + 8x LDS.64 (B) + 32 mma.
// ---------------------------------------------------------------------------
__global__ void __launch_bounds__(256) gemm_fp16(
    const float* __restrict__ A, const float* __restrict__ Bm,
    const float* __restrict__ A2, const float* __restrict__ A3,
    const float* __restrict__ R, float* __restrict__ C,
    const float* __restrict__ log_alpha_ptr)
{
    __shared__ uint32_t Af[2][1024];   // 8 mt * 32 lane * 4 j   (4 KB)
    __shared__ uint32_t Bf[2][2048];   // 32 nt * 32 lane * 2 j  (8 KB)

    const int tid = threadIdx.x, lane = tid & 31, wid = tid >> 5;
    const int g = lane >> 2, tg = lane & 3;
    const int wm = wid >> 2;        // 0..1  (64 m rows each)
    const int wn = wid & 3;         // 0..3  (64 n cols each)
    const int m0 = blockIdx.y * 128, n0 = blockIdx.x * 256;

    // A staging: thread -> row lrA (0..127), k half lkA (0 or 8)
    const int lrA = tid >> 1, lkA = (tid & 1) * 8;
    const int mtA = lrA >> 4, jmA = (lrA & 8) >> 3, jkA = lkA >> 3;
    const int baseA = (mtA * 32 + (lrA & 7) * 4) * 4 + jmA + 2 * jkA;  // + c*4
    // B staging: thread -> row n = tid (0..255), all 16 k
    const int ntB = tid >> 3;
    const int baseB = (ntB * 32 + (tid & 7) * 4) * 2;                  // + c*2 + jk

    const float* Ap  = A  + (size_t)(m0 + lrA) * DQ + lkA;
    const float* Ap2 = A2 ? A2 + (size_t)(m0 + lrA) * DQ + lkA : nullptr;
    const float* Ap3 = A3 ? A3 + (size_t)(m0 + lrA) * DQ + lkA : nullptr;
    const float* Bp  = Bm + (size_t)(n0 + tid) * DQ;

    float av[8];
    float bvv[16];

    // --- prologue: load kt=0 and stage into buf 0 ---
    {
        float4 x0 = *(const float4*)Ap, x1 = *(const float4*)(Ap + 4);
        av[0]=x0.x; av[1]=x0.y; av[2]=x0.z; av[3]=x0.w; av[4]=x1.x; av[5]=x1.y; av[6]=x1.z; av[7]=x1.w;
        if (Ap2) { float4 y0=*(const float4*)Ap2, y1=*(const float4*)(Ap2+4);
            av[0]+=y0.x; av[1]+=y0.y; av[2]+=y0.z; av[3]+=y0.w; av[4]+=y1.x; av[5]+=y1.y; av[6]+=y1.z; av[7]+=y1.w; }
        if (Ap3) { float4 y0=*(const float4*)Ap3, y1=*(const float4*)(Ap3+4);
            av[0]+=y0.x; av[1]+=y0.y; av[2]+=y0.z; av[3]+=y0.w; av[4]+=y1.x; av[5]+=y1.y; av[6]+=y1.z; av[7]+=y1.w; }
        #pragma unroll
        for (int q = 0; q < 4; q++) {
            float4 z = *(const float4*)(Bp + q * 4);
            bvv[q*4+0]=z.x; bvv[q*4+1]=z.y; bvv[q*4+2]=z.z; bvv[q*4+3]=z.w;
        }
        #pragma unroll
        for (int c = 0; c < 4; c++) {
            Af[0][baseA + c * 4]        = pack_h2(av[2*c], av[2*c+1]);
            Bf[0][baseB + c * 2 + 0]    = pack_h2(bvv[2*c],     bvv[2*c+1]);
            Bf[0][baseB + c * 2 + 1]    = pack_h2(bvv[8 + 2*c], bvv[9 + 2*c]);
        }
    }
    __syncthreads();

    float acc[4][8][4];
    #pragma unroll
    for (int i = 0; i < 4; i++) for (int j = 0; j < 8; j++) for (int q = 0; q < 4; q++) acc[i][j][q] = 0.f;

    const int nK = DQ / 16;  // 64
    int buf = 0;
    for (int kt = 0; kt < nK; kt++) {
        // prefetch next k16 into registers
        if (kt < nK - 1) {
            const size_t off = (size_t)(kt + 1) * 16;
            float4 x0 = *(const float4*)(Ap + off), x1 = *(const float4*)(Ap + off + 4);
            av[0]=x0.x; av[1]=x0.y; av[2]=x0.z; av[3]=x0.w; av[4]=x1.x; av[5]=x1.y; av[6]=x1.z; av[7]=x1.w;
            if (Ap2) { float4 y0=*(const float4*)(Ap2+off), y1=*(const float4*)(Ap2+off+4);
                av[0]+=y0.x; av[1]+=y0.y; av[2]+=y0.z; av[3]+=y0.w; av[4]+=y1.x; av[5]+=y1.y; av[6]+=y1.z; av[7]+=y1.w; }
            if (Ap3) { float4 y0=*(const float4*)(Ap3+off), y1=*(const float4*)(Ap3+off+4);
                av[0]+=y0.x; av[1]+=y0.y; av[2]+=y0.z; av[3]+=y0.w; av[4]+=y1.x; av[5]+=y1.y; av[6]+=y1.z; av[7]+=y1.w; }
            #pragma unroll
            for (int q = 0; q < 4; q++) {
                float4 z = *(const float4*)(Bp + off + q * 4);
                bvv[q*4+0]=z.x; bvv[q*4+1]=z.y; bvv[q*4+2]=z.z; bvv[q*4+3]=z.w;
            }
        }
        // compute on current buffer: one k16 step
        {
            uint32_t a[4][4], bb[8][2];
            #pragma unroll
            for (int mi = 0; mi < 4; mi++) {
                uint4 f = *(const uint4*)&Af[buf][((wm * 4 + mi) * 32 + lane) * 4];
                a[mi][0] = f.x; a[mi][1] = f.y; a[mi][2] = f.z; a[mi][3] = f.w;
            }
            #pragma unroll
            for (int ni = 0; ni < 8; ni++) {
                uint2 f = *(const uint2*)&Bf[buf][((wn * 8 + ni) * 32 + lane) * 2];
                bb[ni][0] = f.x; bb[ni][1] = f.y;
            }
            #pragma unroll
            for (int mi = 0; mi < 4; mi++)
                #pragma unroll
                for (int ni = 0; ni < 8; ni++)
                    mma16h(acc[mi][ni], a[mi], bb[ni]);
        }
        // stage prefetched k16 into other buffer
        if (kt < nK - 1) {
            const int nb = buf ^ 1;
            #pragma unroll
            for (int c = 0; c < 4; c++) {
                Af[nb][baseA + c * 4]     = pack_h2(av[2*c], av[2*c+1]);
                Bf[nb][baseB + c * 2 + 0] = pack_h2(bvv[2*c],     bvv[2*c+1]);
                Bf[nb][baseB + c * 2 + 1] = pack_h2(bvv[8 + 2*c], bvv[9 + 2*c]);
            }
            __syncthreads();
            buf = nb;
        }
    }

    const bool useR = (R != nullptr);
    float alpha = 1.0f;
    if (useR) alpha = expf(*log_alpha_ptr);

    #pragma unroll
    for (int mi = 0; mi < 4; mi++) {
        #pragma unroll
        for (int ni = 0; ni < 8; ni++) {
            const int row0 = m0 + wm * 64 + mi * 16 + g;
            const int col  = n0 + wn * 64 + ni * 8 + 2 * tg;
            float2 v0 = make_float2(acc[mi][ni][0], acc[mi][ni][1]);
            float2 v1 = make_float2(acc[mi][ni][2], acc[mi][ni][3]);
            if (useR) {
                float2 r0 = *(const float2*)&R[(size_t)row0 * DQ + col];
                float2 r1 = *(const float2*)&R[(size_t)(row0 + 8) * DQ + col];
                v0.x = fmaf(alpha, v0.x, r0.x); v0.y = fmaf(alpha, v0.y, r0.y);
                v1.x = fmaf(alpha, v1.x, r1.x); v1.y = fmaf(alpha, v1.y, r1.y);
            }
            *(float2*)&C[(size_t)row0 * DQ + col]       = v0;
            *(float2*)&C[(size_t)(row0 + 8) * DQ + col] = v1;
        }
    }
}

// ---------------------------------------------------------------------------
// Intra-chunk kernel (parallel over all (b,chunk)), fp32.  (unchanged)
// ---------------------------------------------------------------------------
__global__ void __launch_bounds__(256) intra_kernel(
    const float* __restrict__ out, const float* __restrict__ decay_ptr)
{
    const int j = blockIdx.x, b = blockIdx.y;
    const float gamma = sigmoidf_(*decay_ptr);
    const float lg = logf(gamma);
    const int tid = threadIdx.x, tx = tid & 15, ty = tid >> 4;
    const int lr = tid >> 2, lk = (tid & 3) << 2;

    __shared__ float SA[16][64];
    __shared__ float SB[16][64];
    __shared__ float Ps[64][64];
    __shared__ float Vs[64][64];

    const float* rbase = out + ((size_t)b * TQ + (size_t)j * CQ) * DQ;
    const int wrow = j * CQ + lr - 1;
    const bool wvalid = (wrow >= 0);
    const float* wptr = out + ((size_t)b * TQ + (size_t)(wvalid ? wrow : 0)) * DQ;

    float acc[4][4];
    #pragma unroll
    for (int i = 0; i < 4; i++) for (int jj = 0; jj < 4; jj++) acc[i][jj] = 0.0f;

    for (int kt = 0; kt < 64; kt++) {
        __syncthreads();
        float4 ra = *(const float4*)(rbase + (size_t)lr * DQ + kt * 16 + lk);
        float4 wa = make_float4(0.f, 0.f, 0.f, 0.f);
        if (wvalid) wa = *(const float4*)(wptr + kt * 16 + lk);
        SA[lk+0][lr] = ra.x; SA[lk+1][lr] = ra.y; SA[lk+2][lr] = ra.z; SA[lk+3][lr] = ra.w;
        SB[lk+0][lr] = wa.x; SB[lk+1][lr] = wa.y; SB[lk+2][lr] = wa.z; SB[lk+3][lr] = wa.w;
        __syncthreads();
        #pragma unroll
        for (int kk = 0; kk < 16; kk++) {
            float af[4], bf[4];
            *(float4*)af = *(const float4*)&SA[kk][ty * 4];
            *(float4*)bf = *(const float4*)&SB[kk][tx * 4];
            #pragma unroll
            for (int i = 0; i < 4; i++)
                #pragma unroll
                for (int jj = 0; jj < 4; jj++)
                    acc[i][jj] = fmaf(af[i], bf[jj], acc[i][jj]);
        }
    }
    __syncthreads();
    #pragma unroll
    for (int i = 0; i < 4; i++)
        #pragma unroll
        for (int jj = 0; jj < 4; jj++) {
            const int c = ty * 4 + i, e = tx * 4 + jj;
            const float msk = (c > e) ? expf(lg * (float)(c - 1 - e)) : 0.0f;
            Ps[c][e] = acc[i][jj] * msk;
        }

    const float* vbase = g_v + ((size_t)b * TQ + (size_t)j * CQ) * DQ;
    float* rd = g_reads + ((size_t)b * TQ + (size_t)j * CQ) * DQ;
    for (int dt = 0; dt < 16; dt++) {
        __syncthreads();
        #pragma unroll
        for (int p = 0; p < 4; p++) {
            const int er = p * 16 + ty;
            *(float4*)&Vs[er][tx * 4] = *(const float4*)(vbase + (size_t)er * DQ + dt * 64 + tx * 4);
        }
        __syncthreads();
        float a2[4][4];
        #pragma unroll
        for (int i = 0; i < 4; i++) for (int jj = 0; jj < 4; jj++) a2[i][jj] = 0.0f;
        #pragma unroll 16
        for (int e = 0; e < 64; e++) {
            float pf[4], vf[4];
            pf[0] = Ps[ty*4+0][e]; pf[1] = Ps[ty*4+1][e]; pf[2] = Ps[ty*4+2][e]; pf[3] = Ps[ty*4+3][e];
            *(float4*)vf = *(const float4*)&Vs[e][tx * 4];
            #pragma unroll
            for (int i = 0; i < 4; i++)
                #pragma unroll
                for (int jj = 0; jj < 4; jj++)
                    a2[i][jj] = fmaf(pf[i], vf[jj], a2[i][jj]);
        }
        #pragma unroll
        for (int i = 0; i < 4; i++) {
            float4 o; o.x = a2[i][0]; o.y = a2[i][1]; o.z = a2[i][2]; o.w = a2[i][3];
            *(float4*)&rd[(size_t)(ty * 4 + i) * DQ + dt * 64 + tx * 4] = o;
        }
    }
}

// ---------------------------------------------------------------------------
// Fused scan kernel (256 threads) — exactly the R10 version (best: 3699 us).
// ---------------------------------------------------------------------------
#define WS_STRIDE 516
#define RS_STRIDE 260
#define US_STRIDE 68
#define SCAN_WORDS (64*WS_STRIDE + 64*RS_STRIDE + 64*US_STRIDE + 520)
#define SCAN_SMEM (SCAN_WORDS * 4)

__global__ void __launch_bounds__(256) scan_kernel(
    const float* __restrict__ out, const float* __restrict__ decay_ptr,
    float* __restrict__ p0, float* __restrict__ p1)
{
    extern __shared__ float sm[];
    float* Ws = sm;                                  // [64][516]
    float* rs = Ws + 64 * WS_STRIDE;                 // [64][260]
    float* us = rs + 64 * RS_STRIDE;                 // [64][68]
    float* prevrow = us + 64 * US_STRIDE;            // [520]

    const int dt = blockIdx.x, es = blockIdx.y, b = blockIdx.z;
    const int d0g = dt * 64;
    const int e0g = es * 512;
    float* pout = (es == 0) ? p0 : p1;

    const int tid = threadIdx.x, lane = tid & 31, wid = tid >> 5;
    const int g = lane >> 2, tg = lane & 3;
    const float gamma = sigmoidf_(*decay_ptr);
    const float lg = logf(gamma);
    const float gC = expf(lg * 64.0f);

    for (int i = tid; i < SCAN_WORDS; i += 256) sm[i] = 0.0f;

    const float* outb = out + (size_t)b * TQ * DQ;
    const float* vb   = g_v + (size_t)b * TQ * DQ;
    float* pb = pout + (size_t)b * TQ * DQ;

    const int wm  = (wid & 3) * 16;
    const int wn4 = (wid >> 2) * 4;

    float gw_it[4];
    #pragma unroll
    for (int it = 0; it < 4; it++) {
        const int c = (tid + it * 256) >> 4;
        gw_it[it] = expf(lg * (float)(63 - c));
    }
    const float s0 = expf(lg * (float)(wm + g));
    const float s1 = expf(lg * (float)(wm + g + 8));

    for (int t = 0; t < NCQ; t++) {
        #pragma unroll
        for (int it = 0; it < 4; it++) {
            const int i = tid + it * 256;
            const int c = i >> 4, x = (i & 15) << 2;
            float4 vv = *(const float4*)(vb + (size_t)(t * 64 + c) * DQ + d0g + x);
            float* dst = us + c * US_STRIDE + x;
            const float gw = gw_it[it];
            dst[0] = f2tf_f(vv.x * gw); dst[1] = f2tf_f(vv.y * gw);
            dst[2] = f2tf_f(vv.z * gw); dst[3] = f2tf_f(vv.w * gw);
        }
        {
            const int e2 = tid * 2;
            float2 pr = make_float2(0.f, 0.f);
            if (t > 0) pr = *(const float2*)(outb + (size_t)(t * 64 - 1) * DQ + e0g + e2);
            prevrow[e2]     = f2tf_f(pr.x);
            prevrow[e2 + 1] = f2tf_f(pr.y);
        }
        #pragma unroll
        for (int it = 0; it < 16; it++) {
            const int i = tid + it * 256;
            const int c = i >> 6, x = (i & 63) << 2;
            float4 rv = *(const float4*)(outb + (size_t)(t * 64 + c) * DQ + e0g + x);
            float* dst = rs + c * RS_STRIDE + x;
            dst[0] = f2tf_f(rv.x); dst[1] = f2tf_f(rv.y);
            dst[2] = f2tf_f(rv.z); dst[3] = f2tf_f(rv.w);
        }
        float4 r1v[16];
        #pragma unroll
        for (int it = 0; it < 16; it++) {
            const int i = tid + it * 256;
            const int c = i >> 6, x = (i & 63) << 2;
            r1v[it] = *(const float4*)(outb + (size_t)(t * 64 + c) * DQ + e0g + 256 + x);
        }

        float acc1[4][4];
        #pragma unroll
        for (int n = 0; n < 4; n++) for (int q = 0; q < 4; q++) acc1[n][q] = 0.f;

        #pragma unroll
        for (int sec = 0; sec < 2; sec++) {
            if (sec == 1) {
                #pragma unroll
                for (int it = 0; it < 16; it++) {
                    const int i = tid + it * 256;
                    const int c = i >> 6, x = (i & 63) << 2;
                    float* dst = rs + c * RS_STRIDE + x;
                    dst[0] = f2tf_f(r1v[it].x); dst[1] = f2tf_f(r1v[it].y);
                    dst[2] = f2tf_f(r1v[it].z); dst[3] = f2tf_f(r1v[it].w);
                }
            }
            __syncthreads();

            if (t > 0) {
                for (int k = 0; k < 32; k++) {
                    uint32_t a[4];
                    a[0] = fu(rs[(wm + g    ) * RS_STRIDE + k * 8 + tg    ]);
                    a[1] = fu(rs[(wm + g + 8) * RS_STRIDE + k * 8 + tg    ]);
                    a[2] = fu(rs[(wm + g    ) * RS_STRIDE + k * 8 + tg + 4]);
                    a[3] = fu(rs[(wm + g + 8) * RS_STRIDE + k * 8 + tg + 4]);
                    #pragma unroll
                    for (int n = 0; n < 4; n++) {
                        const int d = (wn4 + n) * 8 + g;
                        uint32_t bb[2];
                        bb[0] = fu(Ws[d * WS_STRIDE + sec * 256 + k * 8 + tg    ]);
                        bb[1] = fu(Ws[d * WS_STRIDE + sec * 256 + k * 8 + tg + 4]);
                        mma8(acc1[n], a, bb);
                    }
                }
            }

            float acc2[2][8][4];
            #pragma unroll
            for (int m = 0; m < 2; m++) for (int n = 0; n < 8; n++) for (int q = 0; q < 4; q++) acc2[m][n][q] = 0.f;
            const float* prsec = prevrow + sec * 256;
            for (int kk = 0; kk < 8; kk++) {
                const int c0 = kk * 8 + tg - 1;
                const int c1 = kk * 8 + tg + 3;
                const float* r0 = (c0 >= 0) ? (rs + c0 * RS_STRIDE) : prsec;
                const float* r1 = rs + c1 * RS_STRIDE;
                uint32_t a[2][4], bb[8][2];
                #pragma unroll
                for (int m = 0; m < 2; m++) {
                    const int e = (wid * 2 + m) * 16;
                    a[m][0] = fu(r0[e + g    ]);
                    a[m][1] = fu(r0[e + g + 8]);
                    a[m][2] = fu(r1[e + g    ]);
                    a[m][3] = fu(r1[e + g + 8]);
                }
                #pragma unroll
                for (int n = 0; n < 8; n++) {
                    bb[n][0] = fu(us[(kk * 8 + tg    ) * US_STRIDE + n * 8 + g]);
                    bb[n][1] = fu(us[(kk * 8 + tg + 4) * US_STRIDE + n * 8 + g]);
                }
                #pragma unroll
                for (int m = 0; m < 2; m++)
                    #pragma unroll
                    for (int n = 0; n < 8; n++)
                        mma8(acc2[m][n], a[m], bb[n]);
            }
            __syncthreads();

            #pragma unroll
            for (int m = 0; m < 2; m++) {
                const int e = sec * 256 + (wid * 2 + m) * 16;
                #pragma unroll
                for (int n = 0; n < 8; n++) {
                    const int d = n * 8 + 2 * tg;
                    float* w00 = &Ws[(size_t)d       * WS_STRIDE + e + g];
                    float* w01 = &Ws[(size_t)(d + 1) * WS_STRIDE + e + g];
                    float* w10 = &Ws[(size_t)d       * WS_STRIDE + e + g + 8];
                    float* w11 = &Ws[(size_t)(d + 1) * WS_STRIDE + e + g + 8];
                    *w00 = fmaf(gC, *w00, acc2[m][n][0]);
                    *w01 = fmaf(gC, *w01, acc2[m][n][1]);
                    *w10 = fmaf(gC, *w10, acc2[m][n][2]);
                    *w11 = fmaf(gC, *w11, acc2[m][n][3]);
                }
            }
        }

        if (t > 0) {
            const int c0 = wm + g, c1 = wm + g + 8;
            #pragma unroll
            for (int n = 0; n < 4; n++) {
                const int dg = d0g + (wn4 + n) * 8 + 2 * tg;
                float2 v0 = make_float2(acc1[n][0] * s0, acc1[n][1] * s0);
                float2 v1 = make_float2(acc1[n][2] * s1, acc1[n][3] * s1);
                *(float2*)(pb + (size_t)(t * 64 + c0) * DQ + dg) = v0;
                *(float2*)(pb + (size_t)(t * 64 + c1) * DQ + dg) = v1;
            }
        } else {
            #pragma unroll
            for (int it = 0; it < 4; it++) {
                const int i = tid + it * 256;
                const int c = i >> 4, x = (i & 15) << 2;
                *(float4*)(pb + (size_t)c * DQ + d0g + x) = make_float4(0.f, 0.f, 0.f, 0.f);
            }
        }
        __syncthreads();
    }
}

// ---------------------------------------------------------------------------
extern "C" void kernel_launch(void* const* d_in, const int* in_sizes, int n_in,
                              void* d_out, int out_size)
{
    const float* out_in    = (const float*)d_in[0];
    const float* W_write   = (const float*)d_in[1];
    const float* W_read    = (const float*)d_in[2];
    const float* decay     = (const float*)d_in[3];
    const float* log_alpha = (const float*)d_in[4];
    float* outp = (float*)d_out;

    static bool attr_set = false;
    if (!attr_set) {
        cudaFuncSetAttribute(scan_kernel, cudaFuncAttributeMaxDynamicSharedMemorySize, SCAN_SMEM);
        attr_set = true;
    }

    void *pv = nullptr, *pr = nullptr, *pp0 = nullptr, *pp1 = nullptr;
    cudaGetSymbolAddress(&pv, g_v);
    cudaGetSymbolAddress(&pr, g_reads);
    cudaGetSymbolAddress(&pp0, g_p0);
    cudaGetSymbolAddress(&pp1, g_p1);

    dim3 ggemm(DQ / 256, MQ / 128);  // (4, 256)

    // 1) v = out @ W_write^T  (fp16 operands, f32 accumulate)
    gemm_fp16<<<ggemm, 256>>>(out_in, W_write, nullptr, nullptr, nullptr, (float*)pv, nullptr);

    // 2) intra part of reads -> g_reads (parallel over chunks)
    intra_kernel<<<dim3(NCQ, BQ), 256>>>(out_in, decay);

    // 3) whole sequential scan in ONE kernel -> inter partials g_p0/g_p1
    scan_kernel<<<dim3(16, 2, BQ), 256, SCAN_SMEM>>>(out_in, decay, (float*)pp0, (float*)pp1);

    // 4) output = out + alpha * ((g_reads + g_p0 + g_p1) @ W_read^T)
    gemm_fp16<<<ggemm, 256>>>((const float*)pr, W_read, (const float*)pp0, (const float*)pp1,
                              out_in, outp, log_alpha);
}

// round 14
// speedup vs baseline: 1.2245x; 1.0661x over previous
#include <cuda_runtime.h>
#include <cuda_fp16.h>
#include <math.h>
#include <stdint.h>

#define BQ 4
#define TQ 8192
#define DQ 1024
#define CQ 64
#define NCQ 128
#define MQ (BQ*TQ)

// Scratch (static device arrays; no allocation allowed)
__device__ float g_v[(size_t)BQ * TQ * DQ];
__device__ float g_reads[(size_t)BQ * TQ * DQ];   // intra part
__device__ float g_p0[(size_t)BQ * TQ * DQ];      // inter partial, e-slice 0
__device__ float g_p1[(size_t)BQ * TQ * DQ];      // inter partial, e-slice 1

__device__ __forceinline__ float sigmoidf_(float x) { return 1.0f / (1.0f + expf(-x)); }
__device__ __forceinline__ uint32_t fu(float x) { return __float_as_uint(x); }
__device__ __forceinline__ float f2tf_f(float x) {
    uint32_t r;
    asm("cvt.rna.tf32.f32 %0, %1;" : "=r"(r) : "f"(x));
    return __uint_as_float(r);
}
__device__ __forceinline__ uint32_t pack_h2(float lo, float hi) {
    __half2 h = __floats2half2_rn(lo, hi);
    return *(uint32_t*)&h;
}
// tf32 mma (scan): D += A*B, m16n8k8
__device__ __forceinline__ void mma8(float* d, const uint32_t* a, const uint32_t* b) {
    asm volatile(
        "mma.sync.aligned.m16n8k8.row.col.f32.tf32.tf32.f32 "
        "{%0,%1,%2,%3}, {%4,%5,%6,%7}, {%8,%9}, {%0,%1,%2,%3};\n"
        : "+f"(d[0]), "+f"(d[1]), "+f"(d[2]), "+f"(d[3])
        : "r"(a[0]), "r"(a[1]), "r"(a[2]), "r"(a[3]), "r"(b[0]), "r"(b[1]));
}
// fp16 mma (GEMM): D += A*B, m16n8k16, f32 accumulate
__device__ __forceinline__ void mma16h(float* d, const uint32_t* a, const uint32_t* b) {
    asm volatile(
        "mma.sync.aligned.m16n8k16.row.col.f32.f16.f16.f32 "
        "{%0,%1,%2,%3}, {%4,%5,%6,%7}, {%8,%9}, {%0,%1,%2,%3};\n"
        : "+f"(d[0]), "+f"(d[1]), "+f"(d[2]), "+f"(d[3])
        : "r"(a[0]), "r"(a[1]), "r"(a[2]), "r"(a[3]), "r"(b[0]), "r"(b[1]));
}

// ---------------------------------------------------------------------------
// fp16 GEMM: C = R + alpha*((A+A2+A3) @ B^T)   (A2/A3/R optional)
// A: M x 1024, B: 1024 x 1024, row-major K-contiguous. M = 32768.
// Block 128m x 128n, BK=16 double-buffered, 8 warps, warp tile 32x64.
// __launch_bounds__(256, 2) caps regs at 128 -> 2 CTAs/SM (occ 25%).
// Smem holds half2-packed operands in mma-fragment order:
//   A elem (m,k): Af[ (mt*32 + (m&7)*4 + ((k&7)>>1)) * 4 + (m&8)>>3 + 2*((k&8)>>3) ], half k&1
//   B elem (n,k): Bf[ (nt*32 + (n&7)*4 + ((k&7)>>1)) * 2 + ((k&8)>>3) ], half k&1
// Inner loop per warp per k16: 2x LDS.128 (A) + 8x LDS.64 (B) + 16 mma.
// ---------------------------------------------------------------------------
__global__ void __launch_bounds__(256, 2) gemm_fp16(
    const float* __restrict__ A, const float* __restrict__ Bm,
    const float* __restrict__ A2, const float* __restrict__ A3,
    const float* __restrict__ R, float* __restrict__ C,
    const float* __restrict__ log_alpha_ptr)
{
    __shared__ uint32_t Af[2][1024];   // 8 mt * 32 lane * 4 j   (4 KB/buf)
    __shared__ uint32_t Bf[2][1024];   // 16 nt * 32 lane * 2 j  (4 KB/buf)

    const int tid = threadIdx.x, lane = tid & 31, wid = tid >> 5;
    const int g = lane >> 2, tg = lane & 3;
    const int wm = wid >> 1;        // 0..3  (32 m rows each)
    const int wn = wid & 1;         // 0..1  (64 n cols each)
    const int m0 = blockIdx.y * 128, n0 = blockIdx.x * 128;

    // staging: thread -> row lr (0..127), k half lk (0 or 8); same map for A and B
    const int lr = tid >> 1, lk = (tid & 1) * 8;
    const int mt = lr >> 4, jm = (lr & 8) >> 3, jk = lk >> 3;
    const int baseA = (mt * 32 + (lr & 7) * 4) * 4 + jm + 2 * jk;   // + c*4
    const int ntB = lr >> 3;
    const int baseB = (ntB * 32 + (lr & 7) * 4) * 2 + jk;           // + c*2

    const float* Ap  = A  + (size_t)(m0 + lr) * DQ + lk;
    const float* Ap2 = A2 ? A2 + (size_t)(m0 + lr) * DQ + lk : nullptr;
    const float* Ap3 = A3 ? A3 + (size_t)(m0 + lr) * DQ + lk : nullptr;
    const float* Bp  = Bm + (size_t)(n0 + lr) * DQ + lk;

    float av[8];
    float bv[8];

    // --- prologue: load kt=0, stage into buf 0 ---
    {
        float4 x0 = *(const float4*)Ap, x1 = *(const float4*)(Ap + 4);
        av[0]=x0.x; av[1]=x0.y; av[2]=x0.z; av[3]=x0.w; av[4]=x1.x; av[5]=x1.y; av[6]=x1.z; av[7]=x1.w;
        if (Ap2) { float4 y0=*(const float4*)Ap2, y1=*(const float4*)(Ap2+4);
            av[0]+=y0.x; av[1]+=y0.y; av[2]+=y0.z; av[3]+=y0.w; av[4]+=y1.x; av[5]+=y1.y; av[6]+=y1.z; av[7]+=y1.w; }
        if (Ap3) { float4 y0=*(const float4*)Ap3, y1=*(const float4*)(Ap3+4);
            av[0]+=y0.x; av[1]+=y0.y; av[2]+=y0.z; av[3]+=y0.w; av[4]+=y1.x; av[5]+=y1.y; av[6]+=y1.z; av[7]+=y1.w; }
        float4 z0 = *(const float4*)Bp, z1 = *(const float4*)(Bp + 4);
        bv[0]=z0.x; bv[1]=z0.y; bv[2]=z0.z; bv[3]=z0.w; bv[4]=z1.x; bv[5]=z1.y; bv[6]=z1.z; bv[7]=z1.w;
        #pragma unroll
        for (int c = 0; c < 4; c++) {
            Af[0][baseA + c * 4] = pack_h2(av[2*c], av[2*c+1]);
            Bf[0][baseB + c * 2] = pack_h2(bv[2*c], bv[2*c+1]);
        }
    }
    __syncthreads();

    float acc[2][8][4];
    #pragma unroll
    for (int i = 0; i < 2; i++) for (int j = 0; j < 8; j++) for (int q = 0; q < 4; q++) acc[i][j][q] = 0.f;

    const int nK = DQ / 16;  // 64
    int buf = 0;
    for (int kt = 0; kt < nK; kt++) {
        // prefetch next k16 into registers
        if (kt < nK - 1) {
            const size_t off = (size_t)(kt + 1) * 16;
            float4 x0 = *(const float4*)(Ap + off), x1 = *(const float4*)(Ap + off + 4);
            av[0]=x0.x; av[1]=x0.y; av[2]=x0.z; av[3]=x0.w; av[4]=x1.x; av[5]=x1.y; av[6]=x1.z; av[7]=x1.w;
            if (Ap2) { float4 y0=*(const float4*)(Ap2+off), y1=*(const float4*)(Ap2+off+4);
                av[0]+=y0.x; av[1]+=y0.y; av[2]+=y0.z; av[3]+=y0.w; av[4]+=y1.x; av[5]+=y1.y; av[6]+=y1.z; av[7]+=y1.w; }
            if (Ap3) { float4 y0=*(const float4*)(Ap3+off), y1=*(const float4*)(Ap3+off+4);
                av[0]+=y0.x; av[1]+=y0.y; av[2]+=y0.z; av[3]+=y0.w; av[4]+=y1.x; av[5]+=y1.y; av[6]+=y1.z; av[7]+=y1.w; }
            float4 z0 = *(const float4*)(Bp + off), z1 = *(const float4*)(Bp + off + 4);
            bv[0]=z0.x; bv[1]=z0.y; bv[2]=z0.z; bv[3]=z0.w; bv[4]=z1.x; bv[5]=z1.y; bv[6]=z1.z; bv[7]=z1.w;
        }
        // compute on current buffer: one k16 step
        {
            uint32_t a[2][4], bb[8][2];
            #pragma unroll
            for (int mi = 0; mi < 2; mi++) {
                uint4 f = *(const uint4*)&Af[buf][((wm * 2 + mi) * 32 + lane) * 4];
                a[mi][0] = f.x; a[mi][1] = f.y; a[mi][2] = f.z; a[mi][3] = f.w;
            }
            #pragma unroll
            for (int ni = 0; ni < 8; ni++) {
                uint2 f = *(const uint2*)&Bf[buf][((wn * 8 + ni) * 32 + lane) * 2];
                bb[ni][0] = f.x; bb[ni][1] = f.y;
            }
            #pragma unroll
            for (int mi = 0; mi < 2; mi++)
                #pragma unroll
                for (int ni = 0; ni < 8; ni++)
                    mma16h(acc[mi][ni], a[mi], bb[ni]);
        }
        // stage prefetched k16 into other buffer
        if (kt < nK - 1) {
            const int nb = buf ^ 1;
            #pragma unroll
            for (int c = 0; c < 4; c++) {
                Af[nb][baseA + c * 4] = pack_h2(av[2*c], av[2*c+1]);
                Bf[nb][baseB + c * 2] = pack_h2(bv[2*c], bv[2*c+1]);
            }
            __syncthreads();
            buf = nb;
        }
    }

    const bool useR = (R != nullptr);
    float alpha = 1.0f;
    if (useR) alpha = expf(*log_alpha_ptr);

    #pragma unroll
    for (int mi = 0; mi < 2; mi++) {
        #pragma unroll
        for (int ni = 0; ni < 8; ni++) {
            const int row0 = m0 + wm * 32 + mi * 16 + g;
            const int col  = n0 + wn * 64 + ni * 8 + 2 * tg;
            float2 v0 = make_float2(acc[mi][ni][0], acc[mi][ni][1]);
            float2 v1 = make_float2(acc[mi][ni][2], acc[mi][ni][3]);
            if (useR) {
                float2 r0 = *(const float2*)&R[(size_t)row0 * DQ + col];
                float2 r1 = *(const float2*)&R[(size_t)(row0 + 8) * DQ + col];
                v0.x = fmaf(alpha, v0.x, r0.x); v0.y = fmaf(alpha, v0.y, r0.y);
                v1.x = fmaf(alpha, v1.x, r1.x); v1.y = fmaf(alpha, v1.y, r1.y);
            }
            *(float2*)&C[(size_t)row0 * DQ + col]       = v0;
            *(float2*)&C[(size_t)(row0 + 8) * DQ + col] = v1;
        }
    }
}

// ---------------------------------------------------------------------------
// Intra-chunk kernel (parallel over all (b,chunk)), fp32.  (unchanged)
// ---------------------------------------------------------------------------
__global__ void __launch_bounds__(256) intra_kernel(
    const float* __restrict__ out, const float* __restrict__ decay_ptr)
{
    const int j = blockIdx.x, b = blockIdx.y;
    const float gamma = sigmoidf_(*decay_ptr);
    const float lg = logf(gamma);
    const int tid = threadIdx.x, tx = tid & 15, ty = tid >> 4;
    const int lr = tid >> 2, lk = (tid & 3) << 2;

    __shared__ float SA[16][64];
    __shared__ float SB[16][64];
    __shared__ float Ps[64][64];
    __shared__ float Vs[64][64];

    const float* rbase = out + ((size_t)b * TQ + (size_t)j * CQ) * DQ;
    const int wrow = j * CQ + lr - 1;
    const bool wvalid = (wrow >= 0);
    const float* wptr = out + ((size_t)b * TQ + (size_t)(wvalid ? wrow : 0)) * DQ;

    float acc[4][4];
    #pragma unroll
    for (int i = 0; i < 4; i++) for (int jj = 0; jj < 4; jj++) acc[i][jj] = 0.0f;

    for (int kt = 0; kt < 64; kt++) {
        __syncthreads();
        float4 ra = *(const float4*)(rbase + (size_t)lr * DQ + kt * 16 + lk);
        float4 wa = make_float4(0.f, 0.f, 0.f, 0.f);
        if (wvalid) wa = *(const float4*)(wptr + kt * 16 + lk);
        SA[lk+0][lr] = ra.x; SA[lk+1][lr] = ra.y; SA[lk+2][lr] = ra.z; SA[lk+3][lr] = ra.w;
        SB[lk+0][lr] = wa.x; SB[lk+1][lr] = wa.y; SB[lk+2][lr] = wa.z; SB[lk+3][lr] = wa.w;
        __syncthreads();
        #pragma unroll
        for (int kk = 0; kk < 16; kk++) {
            float af[4], bf[4];
            *(float4*)af = *(const float4*)&SA[kk][ty * 4];
            *(float4*)bf = *(const float4*)&SB[kk][tx * 4];
            #pragma unroll
            for (int i = 0; i < 4; i++)
                #pragma unroll
                for (int jj = 0; jj < 4; jj++)
                    acc[i][jj] = fmaf(af[i], bf[jj], acc[i][jj]);
        }
    }
    __syncthreads();
    #pragma unroll
    for (int i = 0; i < 4; i++)
        #pragma unroll
        for (int jj = 0; jj < 4; jj++) {
            const int c = ty * 4 + i, e = tx * 4 + jj;
            const float msk = (c > e) ? expf(lg * (float)(c - 1 - e)) : 0.0f;
            Ps[c][e] = acc[i][jj] * msk;
        }

    const float* vbase = g_v + ((size_t)b * TQ + (size_t)j * CQ) * DQ;
    float* rd = g_reads + ((size_t)b * TQ + (size_t)j * CQ) * DQ;
    for (int dt = 0; dt < 16; dt++) {
        __syncthreads();
        #pragma unroll
        for (int p = 0; p < 4; p++) {
            const int er = p * 16 + ty;
            *(float4*)&Vs[er][tx * 4] = *(const float4*)(vbase + (size_t)er * DQ + dt * 64 + tx * 4);
        }
        __syncthreads();
        float a2[4][4];
        #pragma unroll
        for (int i = 0; i < 4; i++) for (int jj = 0; jj < 4; jj++) a2[i][jj] = 0.0f;
        #pragma unroll 16
        for (int e = 0; e < 64; e++) {
            float pf[4], vf[4];
            pf[0] = Ps[ty*4+0][e]; pf[1] = Ps[ty*4+1][e]; pf[2] = Ps[ty*4+2][e]; pf[3] = Ps[ty*4+3][e];
            *(float4*)vf = *(const float4*)&Vs[e][tx * 4];
            #pragma unroll
            for (int i = 0; i < 4; i++)
                #pragma unroll
                for (int jj = 0; jj < 4; jj++)
                    a2[i][jj] = fmaf(pf[i], vf[jj], a2[i][jj]);
        }
        #pragma unroll
        for (int i = 0; i < 4; i++) {
            float4 o; o.x = a2[i][0]; o.y = a2[i][1]; o.z = a2[i][2]; o.w = a2[i][3];
            *(float4*)&rd[(size_t)(ty * 4 + i) * DQ + dt * 64 + tx * 4] = o;
        }
    }
}

// ---------------------------------------------------------------------------
// Fused scan kernel (256 threads) — exactly the R10 version (best: 3699 us).
// ---------------------------------------------------------------------------
#define WS_STRIDE 516
#define RS_STRIDE 260
#define US_STRIDE 68
#define SCAN_WORDS (64*WS_STRIDE + 64*RS_STRIDE + 64*US_STRIDE + 520)
#define SCAN_SMEM (SCAN_WORDS * 4)

__global__ void __launch_bounds__(256) scan_kernel(
    const float* __restrict__ out, const float* __restrict__ decay_ptr,
    float* __restrict__ p0, float* __restrict__ p1)
{
    extern __shared__ float sm[];
    float* Ws = sm;                                  // [64][516]
    float* rs = Ws + 64 * WS_STRIDE;                 // [64][260]
    float* us = rs + 64 * RS_STRIDE;                 // [64][68]
    float* prevrow = us + 64 * US_STRIDE;            // [520]

    const int dt = blockIdx.x, es = blockIdx.y, b = blockIdx.z;
    const int d0g = dt * 64;
    const int e0g = es * 512;
    float* pout = (es == 0) ? p0 : p1;

    const int tid = threadIdx.x, lane = tid & 31, wid = tid >> 5;
    const int g = lane >> 2, tg = lane & 3;
    const float gamma = sigmoidf_(*decay_ptr);
    const float lg = logf(gamma);
    const float gC = expf(lg * 64.0f);

    for (int i = tid; i < SCAN_WORDS; i += 256) sm[i] = 0.0f;

    const float* outb = out + (size_t)b * TQ * DQ;
    const float* vb   = g_v + (size_t)b * TQ * DQ;
    float* pb = pout + (size_t)b * TQ * DQ;

    const int wm  = (wid & 3) * 16;
    const int wn4 = (wid >> 2) * 4;

    float gw_it[4];
    #pragma unroll
    for (int it = 0; it < 4; it++) {
        const int c = (tid + it * 256) >> 4;
        gw_it[it] = expf(lg * (float)(63 - c));
    }
    const float s0 = expf(lg * (float)(wm + g));
    const float s1 = expf(lg * (float)(wm + g + 8));

    for (int t = 0; t < NCQ; t++) {
        #pragma unroll
        for (int it = 0; it < 4; it++) {
            const int i = tid + it * 256;
            const int c = i >> 4, x = (i & 15) << 2;
            float4 vv = *(const float4*)(vb + (size_t)(t * 64 + c) * DQ + d0g + x);
            float* dst = us + c * US_STRIDE + x;
            const float gw = gw_it[it];
            dst[0] = f2tf_f(vv.x * gw); dst[1] = f2tf_f(vv.y * gw);
            dst[2] = f2tf_f(vv.z * gw); dst[3] = f2tf_f(vv.w * gw);
        }
        {
            const int e2 = tid * 2;
            float2 pr = make_float2(0.f, 0.f);
            if (t > 0) pr = *(const float2*)(outb + (size_t)(t * 64 - 1) * DQ + e0g + e2);
            prevrow[e2]     = f2tf_f(pr.x);
            prevrow[e2 + 1] = f2tf_f(pr.y);
        }
        #pragma unroll
        for (int it = 0; it < 16; it++) {
            const int i = tid + it * 256;
            const int c = i >> 6, x = (i & 63) << 2;
            float4 rv = *(const float4*)(outb + (size_t)(t * 64 + c) * DQ + e0g + x);
            float* dst = rs + c * RS_STRIDE + x;
            dst[0] = f2tf_f(rv.x); dst[1] = f2tf_f(rv.y);
            dst[2] = f2tf_f(rv.z); dst[3] = f2tf_f(rv.w);
        }
        float4 r1v[16];
        #pragma unroll
        for (int it = 0; it < 16; it++) {
            const int i = tid + it * 256;
            const int c = i >> 6, x = (i & 63) << 2;
            r1v[it] = *(const float4*)(outb + (size_t)(t * 64 + c) * DQ + e0g + 256 + x);
        }

        float acc1[4][4];
        #pragma unroll
        for (int n = 0; n < 4; n++) for (int q = 0; q < 4; q++) acc1[n][q] = 0.f;

        #pragma unroll
        for (int sec = 0; sec < 2; sec++) {
            if (sec == 1) {
                #pragma unroll
                for (int it = 0; it < 16; it++) {
                    const int i = tid + it * 256;
                    const int c = i >> 6, x = (i & 63) << 2;
                    float* dst = rs + c * RS_STRIDE + x;
                    dst[0] = f2tf_f(r1v[it].x); dst[1] = f2tf_f(r1v[it].y);
                    dst[2] = f2tf_f(r1v[it].z); dst[3] = f2tf_f(r1v[it].w);
                }
            }
            __syncthreads();

            if (t > 0) {
                for (int k = 0; k < 32; k++) {
                    uint32_t a[4];
                    a[0] = fu(rs[(wm + g    ) * RS_STRIDE + k * 8 + tg    ]);
                    a[1] = fu(rs[(wm + g + 8) * RS_STRIDE + k * 8 + tg    ]);
                    a[2] = fu(rs[(wm + g    ) * RS_STRIDE + k * 8 + tg + 4]);
                    a[3] = fu(rs[(wm + g + 8) * RS_STRIDE + k * 8 + tg + 4]);
                    #pragma unroll
                    for (int n = 0; n < 4; n++) {
                        const int d = (wn4 + n) * 8 + g;
                        uint32_t bb[2];
                        bb[0] = fu(Ws[d * WS_STRIDE + sec * 256 + k * 8 + tg    ]);
                        bb[1] = fu(Ws[d * WS_STRIDE + sec * 256 + k * 8 + tg + 4]);
                        mma8(acc1[n], a, bb);
                    }
                }
            }

            float acc2[2][8][4];
            #pragma unroll
            for (int m = 0; m < 2; m++) for (int n = 0; n < 8; n++) for (int q = 0; q < 4; q++) acc2[m][n][q] = 0.f;
            const float* prsec = prevrow + sec * 256;
            for (int kk = 0; kk < 8; kk++) {
                const int c0 = kk * 8 + tg - 1;
                const int c1 = kk * 8 + tg + 3;
                const float* r0 = (c0 >= 0) ? (rs + c0 * RS_STRIDE) : prsec;
                const float* r1 = rs + c1 * RS_STRIDE;
                uint32_t a[2][4], bb[8][2];
                #pragma unroll
                for (int m = 0; m < 2; m++) {
                    const int e = (wid * 2 + m) * 16;
                    a[m][0] = fu(r0[e + g    ]);
                    a[m][1] = fu(r0[e + g + 8]);
                    a[m][2] = fu(r1[e + g    ]);
                    a[m][3] = fu(r1[e + g + 8]);
                }
                #pragma unroll
                for (int n = 0; n < 8; n++) {
                    bb[n][0] = fu(us[(kk * 8 + tg    ) * US_STRIDE + n * 8 + g]);
                    bb[n][1] = fu(us[(kk * 8 + tg + 4) * US_STRIDE + n * 8 + g]);
                }
                #pragma unroll
                for (int m = 0; m < 2; m++)
                    #pragma unroll
                    for (int n = 0; n < 8; n++)
                        mma8(acc2[m][n], a[m], bb[n]);
            }
            __syncthreads();

            #pragma unroll
            for (int m = 0; m < 2; m++) {
                const int e = sec * 256 + (wid * 2 + m) * 16;
                #pragma unroll
                for (int n = 0; n < 8; n++) {
                    const int d = n * 8 + 2 * tg;
                    float* w00 = &Ws[(size_t)d       * WS_STRIDE + e + g];
                    float* w01 = &Ws[(size_t)(d + 1) * WS_STRIDE + e + g];
                    float* w10 = &Ws[(size_t)d       * WS_STRIDE + e + g + 8];
                    float* w11 = &Ws[(size_t)(d + 1) * WS_STRIDE + e + g + 8];
                    *w00 = fmaf(gC, *w00, acc2[m][n][0]);
                    *w01 = fmaf(gC, *w01, acc2[m][n][1]);
                    *w10 = fmaf(gC, *w10, acc2[m][n][2]);
                    *w11 = fmaf(gC, *w11, acc2[m][n][3]);
                }
            }
        }

        if (t > 0) {
            const int c0 = wm + g, c1 = wm + g + 8;
            #pragma unroll
            for (int n = 0; n < 4; n++) {
                const int dg = d0g + (wn4 + n) * 8 + 2 * tg;
                float2 v0 = make_float2(acc1[n][0] * s0, acc1[n][1] * s0);
                float2 v1 = make_float2(acc1[n][2] * s1, acc1[n][3] * s1);
                *(float2*)(pb + (size_t)(t * 64 + c0) * DQ + dg) = v0;
                *(float2*)(pb + (size_t)(t * 64 + c1) * DQ + dg) = v1;
            }
        } else {
            #pragma unroll
            for (int it = 0; it < 4; it++) {
                const int i = tid + it * 256;
                const int c = i >> 4, x = (i & 15) << 2;
                *(float4*)(pb + (size_t)c * DQ + d0g + x) = make_float4(0.f, 0.f, 0.f, 0.f);
            }
        }
        __syncthreads();
    }
}

// ---------------------------------------------------------------------------
extern "C" void kernel_launch(void* const* d_in, const int* in_sizes, int n_in,
                              void* d_out, int out_size)
{
    const float* out_in    = (const float*)d_in[0];
    const float* W_write   = (const float*)d_in[1];
    const float* W_read    = (const float*)d_in[2];
    const float* decay     = (const float*)d_in[3];
    const float* log_alpha = (const float*)d_in[4];
    float* outp = (float*)d_out;

    static bool attr_set = false;
    if (!attr_set) {
        cudaFuncSetAttribute(scan_kernel, cudaFuncAttributeMaxDynamicSharedMemorySize, SCAN_SMEM);
        attr_set = true;
    }

    void *pv = nullptr, *pr = nullptr, *pp0 = nullptr, *pp1 = nullptr;
    cudaGetSymbolAddress(&pv, g_v);
    cudaGetSymbolAddress(&pr, g_reads);
    cudaGetSymbolAddress(&pp0, g_p0);
    cudaGetSymbolAddress(&pp1, g_p1);

    dim3 ggemm(DQ / 128, MQ / 128);  // (8, 256)

    // 1) v = out @ W_write^T  (fp16 operands, f32 accumulate)
    gemm_fp16<<<ggemm, 256>>>(out_in, W_write, nullptr, nullptr, nullptr, (float*)pv, nullptr);

    // 2) intra part of reads -> g_reads (parallel over chunks)
    intra_kernel<<<dim3(NCQ, BQ), 256>>>(out_in, decay);

    // 3) whole sequential scan in ONE kernel -> inter partials g_p0/g_p1
    scan_kernel<<<dim3(16, 2, BQ), 256, SCAN_SMEM>>>(out_in, decay, (float*)pp0, (float*)pp1);

    // 4) output = out + alpha * ((g_reads + g_p0 + g_p1) @ W_read^T)
    gemm_fp16<<<ggemm, 256>>>((const float*)pr, W_read, (const float*)pp0, (const float*)pp1,
                              out_in, outp, log_alpha);
}

// round 15
// speedup vs baseline: 1.5236x; 1.2443x over previous
#include <cuda_runtime.h>
#include <cuda_fp16.h>
#include <math.h>
#include <stdint.h>

#define BQ 4
#define TQ 8192
#define DQ 1024
#define CQ 64
#define NCQ 128
#define MQ (BQ*TQ)

// Scratch (static device arrays; no allocation allowed)
__device__ float g_v[(size_t)BQ * TQ * DQ];
__device__ float g_reads[(size_t)BQ * TQ * DQ];   // intra part
__device__ float g_p0[(size_t)BQ * TQ * DQ];      // inter partial, e-slice 0
__device__ float g_p1[(size_t)BQ * TQ * DQ];      // inter partial, e-slice 1
__device__ uint32_t g_Ah[(size_t)(MQ/128) * 64 * 1024];  // fragment-ordered half A (64 MB)
__device__ uint32_t g_Bh[(size_t)(DQ/128) * 64 * 1024];  // fragment-ordered half B (2 MB)

__device__ __forceinline__ float sigmoidf_(float x) { return 1.0f / (1.0f + expf(-x)); }
__device__ __forceinline__ uint32_t fu(float x) { return __float_as_uint(x); }
__device__ __forceinline__ float f2tf_f(float x) {
    uint32_t r;
    asm("cvt.rna.tf32.f32 %0, %1;" : "=r"(r) : "f"(x));
    return __uint_as_float(r);
}
__device__ __forceinline__ uint32_t pack_h2(float lo, float hi) {
    __half2 h = __floats2half2_rn(lo, hi);
    return *(uint32_t*)&h;
}
// tf32 mma (scan): D += A*B, m16n8k8
__device__ __forceinline__ void mma8(float* d, const uint32_t* a, const uint32_t* b) {
    asm volatile(
        "mma.sync.aligned.m16n8k8.row.col.f32.tf32.tf32.f32 "
        "{%0,%1,%2,%3}, {%4,%5,%6,%7}, {%8,%9}, {%0,%1,%2,%3};\n"
        : "+f"(d[0]), "+f"(d[1]), "+f"(d[2]), "+f"(d[3])
        : "r"(a[0]), "r"(a[1]), "r"(a[2]), "r"(a[3]), "r"(b[0]), "r"(b[1]));
}
// fp16 mma (GEMM): D += A*B, m16n8k16, f32 accumulate
__device__ __forceinline__ void mma16h(float* d, const uint32_t* a, const uint32_t* b) {
    asm volatile(
        "mma.sync.aligned.m16n8k16.row.col.f32.f16.f16.f32 "
        "{%0,%1,%2,%3}, {%4,%5,%6,%7}, {%8,%9}, {%0,%1,%2,%3};\n"
        : "+f"(d[0]), "+f"(d[1]), "+f"(d[2]), "+f"(d[3])
        : "r"(a[0]), "r"(a[1]), "r"(a[2]), "r"(a[3]), "r"(b[0]), "r"(b[1]));
}

// ---------------------------------------------------------------------------
// conv_frag_a: fragment-permute + fp16-convert (+optional 3-way sum) of an
// A-side matrix. Tile = 128 rows x 16 k. Word w (0..1023) of a tile:
//   q = w>>2 -> mt = q>>5, lane = q&31 (mrow = lane>>2, c = lane&3)
//   j = w&3  -> jm = j&1 (m += 8*jm), jk = j>>1 (k += 8*jk)
//   halves: k = 2c + {0,1}
// Grid: (rowblocks, 64). 256 threads; thread t writes words t*4..t*4+3 (uint4).
// ---------------------------------------------------------------------------
__global__ void __launch_bounds__(256) conv_frag_a(
    const float* __restrict__ in1, const float* __restrict__ in2,
    const float* __restrict__ in3, uint32_t* __restrict__ outw)
{
    const int t = threadIdx.x;
    const int mt = t >> 5, lane = t & 31;
    const int mrow = lane >> 2, c = lane & 3;
    const int mbase = blockIdx.x * 128 + mt * 16 + mrow;
    const int kbase = blockIdx.y * 16 + c * 2;

    uint32_t w[4];
    #pragma unroll
    for (int j = 0; j < 4; j++) {
        const int m = mbase + (j & 1) * 8;
        const int k = kbase + (j >> 1) * 8;
        const float* p = in1 + (size_t)m * DQ + k;
        float lo = p[0], hi = p[1];
        if (in2) { const float* p2 = in2 + (size_t)m * DQ + k; lo += p2[0]; hi += p2[1]; }
        if (in3) { const float* p3 = in3 + (size_t)m * DQ + k; lo += p3[0]; hi += p3[1]; }
        w[j] = pack_h2(lo, hi);
    }
    uint4 o; o.x = w[0]; o.y = w[1]; o.z = w[2]; o.w = w[3];
    *(uint4*)&outw[(((size_t)blockIdx.x * 64 + blockIdx.y) * 1024) + t * 4] = o;
}

// ---------------------------------------------------------------------------
// conv_frag_b: fragment-permute + fp16-convert of a B-side matrix (N x K).
// Word w of a 128n x 16k tile: jk = w&1, q = w>>1 -> nt = q>>5, l2 = q&31
//   (nr = l2>>2, c = l2&3); n = nt*8+nr, k = jk*8 + 2c + {0,1}.
// Grid: (8, 64). 256 threads; thread t writes words t*4..t*4+3.
// ---------------------------------------------------------------------------
__global__ void __launch_bounds__(256) conv_frag_b(
    const float* __restrict__ in, uint32_t* __restrict__ outw)
{
    const int t = threadIdx.x;
    uint32_t w[4];
    #pragma unroll
    for (int j = 0; j < 4; j++) {
        const int wi = t * 4 + j;
        const int jk = wi & 1;
        const int q = wi >> 1;
        const int nt = q >> 5, l2 = q & 31;
        const int nr = l2 >> 2, c = l2 & 3;
        const int n = blockIdx.x * 128 + nt * 8 + nr;
        const int k = blockIdx.y * 16 + jk * 8 + c * 2;
        const float* p = in + (size_t)n * DQ + k;
        w[j] = pack_h2(p[0], p[1]);
    }
    uint4 o; o.x = w[0]; o.y = w[1]; o.z = w[2]; o.w = w[3];
    *(uint4*)&outw[(((size_t)blockIdx.x * 64 + blockIdx.y) * 1024) + t * 4] = o;
}

// ---------------------------------------------------------------------------
// fp16 GEMM on pre-permuted inputs: C = R + alpha*(Ah @ Bh^T)   (R optional)
// Ah: [mblk][kt][1024w] fragment-ordered half2; Bh likewise. M = 32768.
// Block 128m x 128n, BK=16 double-buffered, 8 warps, warp tile 32x64.
// Staging = pure LDG.128 -> STS.128 copy (16 B/thread/tile, no cvt).
// ---------------------------------------------------------------------------
__global__ void __launch_bounds__(256, 2) gemm_h(
    const uint32_t* __restrict__ Ah, const uint32_t* __restrict__ Bh,
    const float* __restrict__ R, float* __restrict__ C,
    const float* __restrict__ log_alpha_ptr)
{
    __shared__ uint32_t Af[2][1024];
    __shared__ uint32_t Bf[2][1024];

    const int tid = threadIdx.x, lane = tid & 31, wid = tid >> 5;
    const int g = lane >> 2, tg = lane & 3;
    const int wm = wid >> 1;        // 0..3  (32 m rows each)
    const int wn = wid & 1;         // 0..1  (64 n cols each)
    const int m0 = blockIdx.y * 128, n0 = blockIdx.x * 128;

    const uint32_t* Ap = Ah + ((size_t)blockIdx.y * 64) * 1024 + tid * 4;
    const uint32_t* Bp = Bh + ((size_t)blockIdx.x * 64) * 1024 + tid * 4;

    uint4 apre, bpre;
    // prologue: kt = 0
    apre = *(const uint4*)Ap;
    bpre = *(const uint4*)Bp;
    *(uint4*)&Af[0][tid * 4] = apre;
    *(uint4*)&Bf[0][tid * 4] = bpre;
    __syncthreads();

    float acc[2][8][4];
    #pragma unroll
    for (int i = 0; i < 2; i++) for (int j = 0; j < 8; j++) for (int q = 0; q < 4; q++) acc[i][j][q] = 0.f;

    const int nK = 64;
    int buf = 0;
    for (int kt = 0; kt < nK; kt++) {
        if (kt < nK - 1) {
            apre = *(const uint4*)(Ap + (size_t)(kt + 1) * 1024);
            bpre = *(const uint4*)(Bp + (size_t)(kt + 1) * 1024);
        }
        // compute one k16 step on current buffer
        {
            uint32_t a[2][4], bb[8][2];
            #pragma unroll
            for (int mi = 0; mi < 2; mi++) {
                uint4 f = *(const uint4*)&Af[buf][((wm * 2 + mi) * 32 + lane) * 4];
                a[mi][0] = f.x; a[mi][1] = f.y; a[mi][2] = f.z; a[mi][3] = f.w;
            }
            #pragma unroll
            for (int ni = 0; ni < 8; ni++) {
                uint2 f = *(const uint2*)&Bf[buf][((wn * 8 + ni) * 32 + lane) * 2];
                bb[ni][0] = f.x; bb[ni][1] = f.y;
            }
            #pragma unroll
            for (int mi = 0; mi < 2; mi++)
                #pragma unroll
                for (int ni = 0; ni < 8; ni++)
                    mma16h(acc[mi][ni], a[mi], bb[ni]);
        }
        if (kt < nK - 1) {
            const int nb = buf ^ 1;
            *(uint4*)&Af[nb][tid * 4] = apre;
            *(uint4*)&Bf[nb][tid * 4] = bpre;
            __syncthreads();
            buf = nb;
        }
    }

    const bool useR = (R != nullptr);
    float alpha = 1.0f;
    if (useR) alpha = expf(*log_alpha_ptr);

    #pragma unroll
    for (int mi = 0; mi < 2; mi++) {
        #pragma unroll
        for (int ni = 0; ni < 8; ni++) {
            const int row0 = m0 + wm * 32 + mi * 16 + g;
            const int col  = n0 + wn * 64 + ni * 8 + 2 * tg;
            float2 v0 = make_float2(acc[mi][ni][0], acc[mi][ni][1]);
            float2 v1 = make_float2(acc[mi][ni][2], acc[mi][ni][3]);
            if (useR) {
                float2 r0 = *(const float2*)&R[(size_t)row0 * DQ + col];
                float2 r1 = *(const float2*)&R[(size_t)(row0 + 8) * DQ + col];
                v0.x = fmaf(alpha, v0.x, r0.x); v0.y = fmaf(alpha, v0.y, r0.y);
                v1.x = fmaf(alpha, v1.x, r1.x); v1.y = fmaf(alpha, v1.y, r1.y);
            }
            *(float2*)&C[(size_t)row0 * DQ + col]       = v0;
            *(float2*)&C[(size_t)(row0 + 8) * DQ + col] = v1;
        }
    }
}

// ---------------------------------------------------------------------------
// Intra-chunk kernel (parallel over all (b,chunk)), fp32.  (unchanged)
// ---------------------------------------------------------------------------
__global__ void __launch_bounds__(256) intra_kernel(
    const float* __restrict__ out, const float* __restrict__ decay_ptr)
{
    const int j = blockIdx.x, b = blockIdx.y;
    const float gamma = sigmoidf_(*decay_ptr);
    const float lg = logf(gamma);
    const int tid = threadIdx.x, tx = tid & 15, ty = tid >> 4;
    const int lr = tid >> 2, lk = (tid & 3) << 2;

    __shared__ float SA[16][64];
    __shared__ float SB[16][64];
    __shared__ float Ps[64][64];
    __shared__ float Vs[64][64];

    const float* rbase = out + ((size_t)b * TQ + (size_t)j * CQ) * DQ;
    const int wrow = j * CQ + lr - 1;
    const bool wvalid = (wrow >= 0);
    const float* wptr = out + ((size_t)b * TQ + (size_t)(wvalid ? wrow : 0)) * DQ;

    float acc[4][4];
    #pragma unroll
    for (int i = 0; i < 4; i++) for (int jj = 0; jj < 4; jj++) acc[i][jj] = 0.0f;

    for (int kt = 0; kt < 64; kt++) {
        __syncthreads();
        float4 ra = *(const float4*)(rbase + (size_t)lr * DQ + kt * 16 + lk);
        float4 wa = make_float4(0.f, 0.f, 0.f, 0.f);
        if (wvalid) wa = *(const float4*)(wptr + kt * 16 + lk);
        SA[lk+0][lr] = ra.x; SA[lk+1][lr] = ra.y; SA[lk+2][lr] = ra.z; SA[lk+3][lr] = ra.w;
        SB[lk+0][lr] = wa.x; SB[lk+1][lr] = wa.y; SB[lk+2][lr] = wa.z; SB[lk+3][lr] = wa.w;
        __syncthreads();
        #pragma unroll
        for (int kk = 0; kk < 16; kk++) {
            float af[4], bf[4];
            *(float4*)af = *(const float4*)&SA[kk][ty * 4];
            *(float4*)bf = *(const float4*)&SB[kk][tx * 4];
            #pragma unroll
            for (int i = 0; i < 4; i++)
                #pragma unroll
                for (int jj = 0; jj < 4; jj++)
                    acc[i][jj] = fmaf(af[i], bf[jj], acc[i][jj]);
        }
    }
    __syncthreads();
    #pragma unroll
    for (int i = 0; i < 4; i++)
        #pragma unroll
        for (int jj = 0; jj < 4; jj++) {
            const int c = ty * 4 + i, e = tx * 4 + jj;
            const float msk = (c > e) ? expf(lg * (float)(c - 1 - e)) : 0.0f;
            Ps[c][e] = acc[i][jj] * msk;
        }

    const float* vbase = g_v + ((size_t)b * TQ + (size_t)j * CQ) * DQ;
    float* rd = g_reads + ((size_t)b * TQ + (size_t)j * CQ) * DQ;
    for (int dt = 0; dt < 16; dt++) {
        __syncthreads();
        #pragma unroll
        for (int p = 0; p < 4; p++) {
            const int er = p * 16 + ty;
            *(float4*)&Vs[er][tx * 4] = *(const float4*)(vbase + (size_t)er * DQ + dt * 64 + tx * 4);
        }
        __syncthreads();
        float a2[4][4];
        #pragma unroll
        for (int i = 0; i < 4; i++) for (int jj = 0; jj < 4; jj++) a2[i][jj] = 0.0f;
        #pragma unroll 16
        for (int e = 0; e < 64; e++) {
            float pf[4], vf[4];
            pf[0] = Ps[ty*4+0][e]; pf[1] = Ps[ty*4+1][e]; pf[2] = Ps[ty*4+2][e]; pf[3] = Ps[ty*4+3][e];
            *(float4*)vf = *(const float4*)&Vs[e][tx * 4];
            #pragma unroll
            for (int i = 0; i < 4; i++)
                #pragma unroll
                for (int jj = 0; jj < 4; jj++)
                    a2[i][jj] = fmaf(pf[i], vf[jj], a2[i][jj]);
        }
        #pragma unroll
        for (int i = 0; i < 4; i++) {
            float4 o; o.x = a2[i][0]; o.y = a2[i][1]; o.z = a2[i][2]; o.w = a2[i][3];
            *(float4*)&rd[(size_t)(ty * 4 + i) * DQ + dt * 64 + tx * 4] = o;
        }
    }
}

// ---------------------------------------------------------------------------
// Fused scan kernel (256 threads) — unchanged from best (R10/R14 version).
// ---------------------------------------------------------------------------
#define WS_STRIDE 516
#define RS_STRIDE 260
#define US_STRIDE 68
#define SCAN_WORDS (64*WS_STRIDE + 64*RS_STRIDE + 64*US_STRIDE + 520)
#define SCAN_SMEM (SCAN_WORDS * 4)

__global__ void __launch_bounds__(256) scan_kernel(
    const float* __restrict__ out, const float* __restrict__ decay_ptr,
    float* __restrict__ p0, float* __restrict__ p1)
{
    extern __shared__ float sm[];
    float* Ws = sm;                                  // [64][516]
    float* rs = Ws + 64 * WS_STRIDE;                 // [64][260]
    float* us = rs + 64 * RS_STRIDE;                 // [64][68]
    float* prevrow = us + 64 * US_STRIDE;            // [520]

    const int dt = blockIdx.x, es = blockIdx.y, b = blockIdx.z;
    const int d0g = dt * 64;
    const int e0g = es * 512;
    float* pout = (es == 0) ? p0 : p1;

    const int tid = threadIdx.x, lane = tid & 31, wid = tid >> 5;
    const int g = lane >> 2, tg = lane & 3;
    const float gamma = sigmoidf_(*decay_ptr);
    const float lg = logf(gamma);
    const float gC = expf(lg * 64.0f);

    for (int i = tid; i < SCAN_WORDS; i += 256) sm[i] = 0.0f;

    const float* outb = out + (size_t)b * TQ * DQ;
    const float* vb   = g_v + (size_t)b * TQ * DQ;
    float* pb = pout + (size_t)b * TQ * DQ;

    const int wm  = (wid & 3) * 16;
    const int wn4 = (wid >> 2) * 4;

    float gw_it[4];
    #pragma unroll
    for (int it = 0; it < 4; it++) {
        const int c = (tid + it * 256) >> 4;
        gw_it[it] = expf(lg * (float)(63 - c));
    }
    const float s0 = expf(lg * (float)(wm + g));
    const float s1 = expf(lg * (float)(wm + g + 8));

    for (int t = 0; t < NCQ; t++) {
        #pragma unroll
        for (int it = 0; it < 4; it++) {
            const int i = tid + it * 256;
            const int c = i >> 4, x = (i & 15) << 2;
            float4 vv = *(const float4*)(vb + (size_t)(t * 64 + c) * DQ + d0g + x);
            float* dst = us + c * US_STRIDE + x;
            const float gw = gw_it[it];
            dst[0] = f2tf_f(vv.x * gw); dst[1] = f2tf_f(vv.y * gw);
            dst[2] = f2tf_f(vv.z * gw); dst[3] = f2tf_f(vv.w * gw);
        }
        {
            const int e2 = tid * 2;
            float2 pr = make_float2(0.f, 0.f);
            if (t > 0) pr = *(const float2*)(outb + (size_t)(t * 64 - 1) * DQ + e0g + e2);
            prevrow[e2]     = f2tf_f(pr.x);
            prevrow[e2 + 1] = f2tf_f(pr.y);
        }
        #pragma unroll
        for (int it = 0; it < 16; it++) {
            const int i = tid + it * 256;
            const int c = i >> 6, x = (i & 63) << 2;
            float4 rv = *(const float4*)(outb + (size_t)(t * 64 + c) * DQ + e0g + x);
            float* dst = rs + c * RS_STRIDE + x;
            dst[0] = f2tf_f(rv.x); dst[1] = f2tf_f(rv.y);
            dst[2] = f2tf_f(rv.z); dst[3] = f2tf_f(rv.w);
        }
        float4 r1v[16];
        #pragma unroll
        for (int it = 0; it < 16; it++) {
            const int i = tid + it * 256;
            const int c = i >> 6, x = (i & 63) << 2;
            r1v[it] = *(const float4*)(outb + (size_t)(t * 64 + c) * DQ + e0g + 256 + x);
        }

        float acc1[4][4];
        #pragma unroll
        for (int n = 0; n < 4; n++) for (int q = 0; q < 4; q++) acc1[n][q] = 0.f;

        #pragma unroll
        for (int sec = 0; sec < 2; sec++) {
            if (sec == 1) {
                #pragma unroll
                for (int it = 0; it < 16; it++) {
                    const int i = tid + it * 256;
                    const int c = i >> 6, x = (i & 63) << 2;
                    float* dst = rs + c * RS_STRIDE + x;
                    dst[0] = f2tf_f(r1v[it].x); dst[1] = f2tf_f(r1v[it].y);
                    dst[2] = f2tf_f(r1v[it].z); dst[3] = f2tf_f(r1v[it].w);
                }
            }
            __syncthreads();

            if (t > 0) {
                for (int k = 0; k < 32; k++) {
                    uint32_t a[4];
                    a[0] = fu(rs[(wm + g    ) * RS_STRIDE + k * 8 + tg    ]);
                    a[1] = fu(rs[(wm + g + 8) * RS_STRIDE + k * 8 + tg    ]);
                    a[2] = fu(rs[(wm + g    ) * RS_STRIDE + k * 8 + tg + 4]);
                    a[3] = fu(rs[(wm + g + 8) * RS_STRIDE + k * 8 + tg + 4]);
                    #pragma unroll
                    for (int n = 0; n < 4; n++) {
                        const int d = (wn4 + n) * 8 + g;
                        uint32_t bb[2];
                        bb[0] = fu(Ws[d * WS_STRIDE + sec * 256 + k * 8 + tg    ]);
                        bb[1] = fu(Ws[d * WS_STRIDE + sec * 256 + k * 8 + tg + 4]);
                        mma8(acc1[n], a, bb);
                    }
                }
            }

            float acc2[2][8][4];
            #pragma unroll
            for (int m = 0; m < 2; m++) for (int n = 0; n < 8; n++) for (int q = 0; q < 4; q++) acc2[m][n][q] = 0.f;
            const float* prsec = prevrow + sec * 256;
            for (int kk = 0; kk < 8; kk++) {
                const int c0 = kk * 8 + tg - 1;
                const int c1 = kk * 8 + tg + 3;
                const float* r0 = (c0 >= 0) ? (rs + c0 * RS_STRIDE) : prsec;
                const float* r1 = rs + c1 * RS_STRIDE;
                uint32_t a[2][4], bb[8][2];
                #pragma unroll
                for (int m = 0; m < 2; m++) {
                    const int e = (wid * 2 + m) * 16;
                    a[m][0] = fu(r0[e + g    ]);
                    a[m][1] = fu(r0[e + g + 8]);
                    a[m][2] = fu(r1[e + g    ]);
                    a[m][3] = fu(r1[e + g + 8]);
                }
                #pragma unroll
                for (int n = 0; n < 8; n++) {
                    bb[n][0] = fu(us[(kk * 8 + tg    ) * US_STRIDE + n * 8 + g]);
                    bb[n][1] = fu(us[(kk * 8 + tg + 4) * US_STRIDE + n * 8 + g]);
                }
                #pragma unroll
                for (int m = 0; m < 2; m++)
                    #pragma unroll
                    for (int n = 0; n < 8; n++)
                        mma8(acc2[m][n], a[m], bb[n]);
            }
            __syncthreads();

            #pragma unroll
            for (int m = 0; m < 2; m++) {
                const int e = sec * 256 + (wid * 2 + m) * 16;
                #pragma unroll
                for (int n = 0; n < 8; n++) {
                    const int d = n * 8 + 2 * tg;
                    float* w00 = &Ws[(size_t)d       * WS_STRIDE + e + g];
                    float* w01 = &Ws[(size_t)(d + 1) * WS_STRIDE + e + g];
                    float* w10 = &Ws[(size_t)d       * WS_STRIDE + e + g + 8];
                    float* w11 = &Ws[(size_t)(d + 1) * WS_STRIDE + e + g + 8];
                    *w00 = fmaf(gC, *w00, acc2[m][n][0]);
                    *w01 = fmaf(gC, *w01, acc2[m][n][1]);
                    *w10 = fmaf(gC, *w10, acc2[m][n][2]);
                    *w11 = fmaf(gC, *w11, acc2[m][n][3]);
                }
            }
        }

        if (t > 0) {
            const int c0 = wm + g, c1 = wm + g + 8;
            #pragma unroll
            for (int n = 0; n < 4; n++) {
                const int dg = d0g + (wn4 + n) * 8 + 2 * tg;
                float2 v0 = make_float2(acc1[n][0] * s0, acc1[n][1] * s0);
                float2 v1 = make_float2(acc1[n][2] * s1, acc1[n][3] * s1);
                *(float2*)(pb + (size_t)(t * 64 + c0) * DQ + dg) = v0;
                *(float2*)(pb + (size_t)(t * 64 + c1) * DQ + dg) = v1;
            }
        } else {
            #pragma unroll
            for (int it = 0; it < 4; it++) {
                const int i = tid + it * 256;
                const int c = i >> 4, x = (i & 15) << 2;
                *(float4*)(pb + (size_t)c * DQ + d0g + x) = make_float4(0.f, 0.f, 0.f, 0.f);
            }
        }
        __syncthreads();
    }
}

// ---------------------------------------------------------------------------
extern "C" void kernel_launch(void* const* d_in, const int* in_sizes, int n_in,
                              void* d_out, int out_size)
{
    const float* out_in    = (const float*)d_in[0];
    const float* W_write   = (const float*)d_in[1];
    const float* W_read    = (const float*)d_in[2];
    const float* decay     = (const float*)d_in[3];
    const float* log_alpha = (const float*)d_in[4];
    float* outp = (float*)d_out;

    static bool attr_set = false;
    if (!attr_set) {
        cudaFuncSetAttribute(scan_kernel, cudaFuncAttributeMaxDynamicSharedMemorySize, SCAN_SMEM);
        attr_set = true;
    }

    void *pv = nullptr, *pr = nullptr, *pp0 = nullptr, *pp1 = nullptr, *pah = nullptr, *pbh = nullptr;
    cudaGetSymbolAddress(&pv, g_v);
    cudaGetSymbolAddress(&pr, g_reads);
    cudaGetSymbolAddress(&pp0, g_p0);
    cudaGetSymbolAddress(&pp1, g_p1);
    cudaGetSymbolAddress(&pah, g_Ah);
    cudaGetSymbolAddress(&pbh, g_Bh);
    uint32_t* Ah = (uint32_t*)pah;
    uint32_t* Bh = (uint32_t*)pbh;

    dim3 ggemm(DQ / 128, MQ / 128);  // (8, 256)

    // 1) convert out and W_write into fragment-ordered fp16; GEMM1: v
    conv_frag_a<<<dim3(MQ / 128, 64), 256>>>(out_in, nullptr, nullptr, Ah);
    conv_frag_b<<<dim3(DQ / 128, 64), 256>>>(W_write, Bh);
    gemm_h<<<ggemm, 256>>>(Ah, Bh, nullptr, (float*)pv, nullptr);

    // 2) intra part of reads -> g_reads (parallel over chunks)
    intra_kernel<<<dim3(NCQ, BQ), 256>>>(out_in, decay);

    // 3) whole sequential scan in ONE kernel -> inter partials g_p0/g_p1
    scan_kernel<<<dim3(16, 2, BQ), 256, SCAN_SMEM>>>(out_in, decay, (float*)pp0, (float*)pp1);

    // 4) sum+convert (g_reads + g_p0 + g_p1) and W_read; GEMM2: output
    conv_frag_a<<<dim3(MQ / 128, 64), 256>>>((const float*)pr, (const float*)pp0, (const float*)pp1, Ah);
    conv_frag_b<<<dim3(DQ / 128, 64), 256>>>(W_read, Bh);
    gemm_h<<<ggemm, 256>>>(Ah, Bh, out_in, outp, log_alpha);
}

// round 16
// speedup vs baseline: 1.6836x; 1.1051x over previous
#include <cuda_runtime.h>
#include <cuda_fp16.h>
#include <math.h>
#include <stdint.h>

#define BQ 4
#define TQ 8192
#define DQ 1024
#define CQ 64
#define NCQ 128
#define MQ (BQ*TQ)

// Scratch (static device arrays; no allocation allowed)
__device__ float g_v[(size_t)BQ * TQ * DQ];
__device__ float g_reads[(size_t)BQ * TQ * DQ];   // intra part
__device__ float g_p0[(size_t)BQ * TQ * DQ];      // inter partial, e-slice 0
__device__ float g_p1[(size_t)BQ * TQ * DQ];      // inter partial, e-slice 1
__device__ uint32_t g_Ah[(size_t)(MQ/128) * 64 * 1024];  // fragment-ordered half A (64 MB)
__device__ uint32_t g_Bh[(size_t)(DQ/128) * 64 * 1024];  // fragment-ordered half B (W_write)
__device__ uint32_t g_Bh2[(size_t)(DQ/128) * 64 * 1024]; // fragment-ordered half B (W_read)

__device__ __forceinline__ float sigmoidf_(float x) { return 1.0f / (1.0f + expf(-x)); }
__device__ __forceinline__ uint32_t fu(float x) { return __float_as_uint(x); }
__device__ __forceinline__ float f2tf_f(float x) {
    uint32_t r;
    asm("cvt.rna.tf32.f32 %0, %1;" : "=r"(r) : "f"(x));
    return __uint_as_float(r);
}
__device__ __forceinline__ uint32_t pack_h2(float lo, float hi) {
    __half2 h = __floats2half2_rn(lo, hi);
    return *(uint32_t*)&h;
}
// tf32 mma (scan): D += A*B, m16n8k8
__device__ __forceinline__ void mma8(float* d, const uint32_t* a, const uint32_t* b) {
    asm volatile(
        "mma.sync.aligned.m16n8k8.row.col.f32.tf32.tf32.f32 "
        "{%0,%1,%2,%3}, {%4,%5,%6,%7}, {%8,%9}, {%0,%1,%2,%3};\n"
        : "+f"(d[0]), "+f"(d[1]), "+f"(d[2]), "+f"(d[3])
        : "r"(a[0]), "r"(a[1]), "r"(a[2]), "r"(a[3]), "r"(b[0]), "r"(b[1]));
}
// fp16 mma (GEMM): D += A*B, m16n8k16, f32 accumulate
__device__ __forceinline__ void mma16h(float* d, const uint32_t* a, const uint32_t* b) {
    asm volatile(
        "mma.sync.aligned.m16n8k16.row.col.f32.f16.f16.f32 "
        "{%0,%1,%2,%3}, {%4,%5,%6,%7}, {%8,%9}, {%0,%1,%2,%3};\n"
        : "+f"(d[0]), "+f"(d[1]), "+f"(d[2]), "+f"(d[3])
        : "r"(a[0]), "r"(a[1]), "r"(a[2]), "r"(a[3]), "r"(b[0]), "r"(b[1]));
}

// ---------------------------------------------------------------------------
// conv_frag_a: fragment-permute + fp16-convert (+optional 3-way sum), A side.
// ---------------------------------------------------------------------------
__global__ void __launch_bounds__(256) conv_frag_a(
    const float* __restrict__ in1, const float* __restrict__ in2,
    const float* __restrict__ in3, uint32_t* __restrict__ outw)
{
    const int t = threadIdx.x;
    const int mt = t >> 5, lane = t & 31;
    const int mrow = lane >> 2, c = lane & 3;
    const int mbase = blockIdx.x * 128 + mt * 16 + mrow;
    const int kbase = blockIdx.y * 16 + c * 2;

    uint32_t w[4];
    #pragma unroll
    for (int j = 0; j < 4; j++) {
        const int m = mbase + (j & 1) * 8;
        const int k = kbase + (j >> 1) * 8;
        const float* p = in1 + (size_t)m * DQ + k;
        float lo = p[0], hi = p[1];
        if (in2) { const float* p2 = in2 + (size_t)m * DQ + k; lo += p2[0]; hi += p2[1]; }
        if (in3) { const float* p3 = in3 + (size_t)m * DQ + k; lo += p3[0]; hi += p3[1]; }
        w[j] = pack_h2(lo, hi);
    }
    uint4 o; o.x = w[0]; o.y = w[1]; o.z = w[2]; o.w = w[3];
    *(uint4*)&outw[(((size_t)blockIdx.x * 64 + blockIdx.y) * 1024) + t * 4] = o;
}

// ---------------------------------------------------------------------------
// conv_frag_b: fragment-permute + fp16-convert, B side (N x K).
// ---------------------------------------------------------------------------
__global__ void __launch_bounds__(256) conv_frag_b(
    const float* __restrict__ in, uint32_t* __restrict__ outw)
{
    const int t = threadIdx.x;
    uint32_t w[4];
    #pragma unroll
    for (int j = 0; j < 4; j++) {
        const int wi = t * 4 + j;
        const int jk = wi & 1;
        const int q = wi >> 1;
        const int nt = q >> 5, l2 = q & 31;
        const int nr = l2 >> 2, c = l2 & 3;
        const int n = blockIdx.x * 128 + nt * 8 + nr;
        const int k = blockIdx.y * 16 + jk * 8 + c * 2;
        const float* p = in + (size_t)n * DQ + k;
        w[j] = pack_h2(p[0], p[1]);
    }
    uint4 o; o.x = w[0]; o.y = w[1]; o.z = w[2]; o.w = w[3];
    *(uint4*)&outw[(((size_t)blockIdx.x * 64 + blockIdx.y) * 1024) + t * 4] = o;
}

// ---------------------------------------------------------------------------
// fp16 GEMM on pre-permuted inputs: C = R + alpha*(Ah @ Bh^T)   (R optional)
// Block 128m x 128n, BK=16 double-buffered, 8 warps, warp tile 32x64.
// ---------------------------------------------------------------------------
__global__ void __launch_bounds__(256, 2) gemm_h(
    const uint32_t* __restrict__ Ah, const uint32_t* __restrict__ Bh,
    const float* __restrict__ R, float* __restrict__ C,
    const float* __restrict__ log_alpha_ptr)
{
    __shared__ uint32_t Af[2][1024];
    __shared__ uint32_t Bf[2][1024];

    const int tid = threadIdx.x, lane = tid & 31, wid = tid >> 5;
    const int g = lane >> 2, tg = lane & 3;
    const int wm = wid >> 1;
    const int wn = wid & 1;
    const int m0 = blockIdx.y * 128, n0 = blockIdx.x * 128;

    const uint32_t* Ap = Ah + ((size_t)blockIdx.y * 64) * 1024 + tid * 4;
    const uint32_t* Bp = Bh + ((size_t)blockIdx.x * 64) * 1024 + tid * 4;

    uint4 apre, bpre;
    apre = *(const uint4*)Ap;
    bpre = *(const uint4*)Bp;
    *(uint4*)&Af[0][tid * 4] = apre;
    *(uint4*)&Bf[0][tid * 4] = bpre;
    __syncthreads();

    float acc[2][8][4];
    #pragma unroll
    for (int i = 0; i < 2; i++) for (int j = 0; j < 8; j++) for (int q = 0; q < 4; q++) acc[i][j][q] = 0.f;

    const int nK = 64;
    int buf = 0;
    for (int kt = 0; kt < nK; kt++) {
        if (kt < nK - 1) {
            apre = *(const uint4*)(Ap + (size_t)(kt + 1) * 1024);
            bpre = *(const uint4*)(Bp + (size_t)(kt + 1) * 1024);
        }
        {
            uint32_t a[2][4], bb[8][2];
            #pragma unroll
            for (int mi = 0; mi < 2; mi++) {
                uint4 f = *(const uint4*)&Af[buf][((wm * 2 + mi) * 32 + lane) * 4];
                a[mi][0] = f.x; a[mi][1] = f.y; a[mi][2] = f.z; a[mi][3] = f.w;
            }
            #pragma unroll
            for (int ni = 0; ni < 8; ni++) {
                uint2 f = *(const uint2*)&Bf[buf][((wn * 8 + ni) * 32 + lane) * 2];
                bb[ni][0] = f.x; bb[ni][1] = f.y;
            }
            #pragma unroll
            for (int mi = 0; mi < 2; mi++)
                #pragma unroll
                for (int ni = 0; ni < 8; ni++)
                    mma16h(acc[mi][ni], a[mi], bb[ni]);
        }
        if (kt < nK - 1) {
            const int nb = buf ^ 1;
            *(uint4*)&Af[nb][tid * 4] = apre;
            *(uint4*)&Bf[nb][tid * 4] = bpre;
            __syncthreads();
            buf = nb;
        }
    }

    const bool useR = (R != nullptr);
    float alpha = 1.0f;
    if (useR) alpha = expf(*log_alpha_ptr);

    #pragma unroll
    for (int mi = 0; mi < 2; mi++) {
        #pragma unroll
        for (int ni = 0; ni < 8; ni++) {
            const int row0 = m0 + wm * 32 + mi * 16 + g;
            const int col  = n0 + wn * 64 + ni * 8 + 2 * tg;
            float2 v0 = make_float2(acc[mi][ni][0], acc[mi][ni][1]);
            float2 v1 = make_float2(acc[mi][ni][2], acc[mi][ni][3]);
            if (useR) {
                float2 r0 = *(const float2*)&R[(size_t)row0 * DQ + col];
                float2 r1 = *(const float2*)&R[(size_t)(row0 + 8) * DQ + col];
                v0.x = fmaf(alpha, v0.x, r0.x); v0.y = fmaf(alpha, v0.y, r0.y);
                v1.x = fmaf(alpha, v1.x, r1.x); v1.y = fmaf(alpha, v1.y, r1.y);
            }
            *(float2*)&C[(size_t)row0 * DQ + col]       = v0;
            *(float2*)&C[(size_t)(row0 + 8) * DQ + col] = v1;
        }
    }
}

// ---------------------------------------------------------------------------
// Intra-chunk kernel (parallel over all (b,chunk)), fp32.  (unchanged)
// ---------------------------------------------------------------------------
__global__ void __launch_bounds__(256) intra_kernel(
    const float* __restrict__ out, const float* __restrict__ decay_ptr)
{
    const int j = blockIdx.x, b = blockIdx.y;
    const float gamma = sigmoidf_(*decay_ptr);
    const float lg = logf(gamma);
    const int tid = threadIdx.x, tx = tid & 15, ty = tid >> 4;
    const int lr = tid >> 2, lk = (tid & 3) << 2;

    __shared__ float SA[16][64];
    __shared__ float SB[16][64];
    __shared__ float Ps[64][64];
    __shared__ float Vs[64][64];

    const float* rbase = out + ((size_t)b * TQ + (size_t)j * CQ) * DQ;
    const int wrow = j * CQ + lr - 1;
    const bool wvalid = (wrow >= 0);
    const float* wptr = out + ((size_t)b * TQ + (size_t)(wvalid ? wrow : 0)) * DQ;

    float acc[4][4];
    #pragma unroll
    for (int i = 0; i < 4; i++) for (int jj = 0; jj < 4; jj++) acc[i][jj] = 0.0f;

    for (int kt = 0; kt < 64; kt++) {
        __syncthreads();
        float4 ra = *(const float4*)(rbase + (size_t)lr * DQ + kt * 16 + lk);
        float4 wa = make_float4(0.f, 0.f, 0.f, 0.f);
        if (wvalid) wa = *(const float4*)(wptr + kt * 16 + lk);
        SA[lk+0][lr] = ra.x; SA[lk+1][lr] = ra.y; SA[lk+2][lr] = ra.z; SA[lk+3][lr] = ra.w;
        SB[lk+0][lr] = wa.x; SB[lk+1][lr] = wa.y; SB[lk+2][lr] = wa.z; SB[lk+3][lr] = wa.w;
        __syncthreads();
        #pragma unroll
        for (int kk = 0; kk < 16; kk++) {
            float af[4], bf[4];
            *(float4*)af = *(const float4*)&SA[kk][ty * 4];
            *(float4*)bf = *(const float4*)&SB[kk][tx * 4];
            #pragma unroll
            for (int i = 0; i < 4; i++)
                #pragma unroll
                for (int jj = 0; jj < 4; jj++)
                    acc[i][jj] = fmaf(af[i], bf[jj], acc[i][jj]);
        }
    }
    __syncthreads();
    #pragma unroll
    for (int i = 0; i < 4; i++)
        #pragma unroll
        for (int jj = 0; jj < 4; jj++) {
            const int c = ty * 4 + i, e = tx * 4 + jj;
            const float msk = (c > e) ? expf(lg * (float)(c - 1 - e)) : 0.0f;
            Ps[c][e] = acc[i][jj] * msk;
        }

    const float* vbase = g_v + ((size_t)b * TQ + (size_t)j * CQ) * DQ;
    float* rd = g_reads + ((size_t)b * TQ + (size_t)j * CQ) * DQ;
    for (int dt = 0; dt < 16; dt++) {
        __syncthreads();
        #pragma unroll
        for (int p = 0; p < 4; p++) {
            const int er = p * 16 + ty;
            *(float4*)&Vs[er][tx * 4] = *(const float4*)(vbase + (size_t)er * DQ + dt * 64 + tx * 4);
        }
        __syncthreads();
        float a2[4][4];
        #pragma unroll
        for (int i = 0; i < 4; i++) for (int jj = 0; jj < 4; jj++) a2[i][jj] = 0.0f;
        #pragma unroll 16
        for (int e = 0; e < 64; e++) {
            float pf[4], vf[4];
            pf[0] = Ps[ty*4+0][e]; pf[1] = Ps[ty*4+1][e]; pf[2] = Ps[ty*4+2][e]; pf[3] = Ps[ty*4+3][e];
            *(float4*)vf = *(const float4*)&Vs[e][tx * 4];
            #pragma unroll
            for (int i = 0; i < 4; i++)
                #pragma unroll
                for (int jj = 0; jj < 4; jj++)
                    a2[i][jj] = fmaf(pf[i], vf[jj], a2[i][jj]);
        }
        #pragma unroll
        for (int i = 0; i < 4; i++) {
            float4 o; o.x = a2[i][0]; o.y = a2[i][1]; o.z = a2[i][2]; o.w = a2[i][3];
            *(float4*)&rd[(size_t)(ty * 4 + i) * DQ + dt * 64 + tx * 4] = o;
        }
    }
}

// ---------------------------------------------------------------------------
// Fused scan kernel (256 threads) — unchanged (best version).
// ---------------------------------------------------------------------------
#define WS_STRIDE 516
#define RS_STRIDE 260
#define US_STRIDE 68
#define SCAN_WORDS (64*WS_STRIDE + 64*RS_STRIDE + 64*US_STRIDE + 520)
#define SCAN_SMEM (SCAN_WORDS * 4)

__global__ void __launch_bounds__(256) scan_kernel(
    const float* __restrict__ out, const float* __restrict__ decay_ptr,
    float* __restrict__ p0, float* __restrict__ p1)
{
    extern __shared__ float sm[];
    float* Ws = sm;
    float* rs = Ws + 64 * WS_STRIDE;
    float* us = rs + 64 * RS_STRIDE;
    float* prevrow = us + 64 * US_STRIDE;

    const int dt = blockIdx.x, es = blockIdx.y, b = blockIdx.z;
    const int d0g = dt * 64;
    const int e0g = es * 512;
    float* pout = (es == 0) ? p0 : p1;

    const int tid = threadIdx.x, lane = tid & 31, wid = tid >> 5;
    const int g = lane >> 2, tg = lane & 3;
    const float gamma = sigmoidf_(*decay_ptr);
    const float lg = logf(gamma);
    const float gC = expf(lg * 64.0f);

    for (int i = tid; i < SCAN_WORDS; i += 256) sm[i] = 0.0f;

    const float* outb = out + (size_t)b * TQ * DQ;
    const float* vb   = g_v + (size_t)b * TQ * DQ;
    float* pb = pout + (size_t)b * TQ * DQ;

    const int wm  = (wid & 3) * 16;
    const int wn4 = (wid >> 2) * 4;

    float gw_it[4];
    #pragma unroll
    for (int it = 0; it < 4; it++) {
        const int c = (tid + it * 256) >> 4;
        gw_it[it] = expf(lg * (float)(63 - c));
    }
    const float s0 = expf(lg * (float)(wm + g));
    const float s1 = expf(lg * (float)(wm + g + 8));

    for (int t = 0; t < NCQ; t++) {
        #pragma unroll
        for (int it = 0; it < 4; it++) {
            const int i = tid + it * 256;
            const int c = i >> 4, x = (i & 15) << 2;
            float4 vv = *(const float4*)(vb + (size_t)(t * 64 + c) * DQ + d0g + x);
            float* dst = us + c * US_STRIDE + x;
            const float gw = gw_it[it];
            dst[0] = f2tf_f(vv.x * gw); dst[1] = f2tf_f(vv.y * gw);
            dst[2] = f2tf_f(vv.z * gw); dst[3] = f2tf_f(vv.w * gw);
        }
        {
            const int e2 = tid * 2;
            float2 pr = make_float2(0.f, 0.f);
            if (t > 0) pr = *(const float2*)(outb + (size_t)(t * 64 - 1) * DQ + e0g + e2);
            prevrow[e2]     = f2tf_f(pr.x);
            prevrow[e2 + 1] = f2tf_f(pr.y);
        }
        #pragma unroll
        for (int it = 0; it < 16; it++) {
            const int i = tid + it * 256;
            const int c = i >> 6, x = (i & 63) << 2;
            float4 rv = *(const float4*)(outb + (size_t)(t * 64 + c) * DQ + e0g + x);
            float* dst = rs + c * RS_STRIDE + x;
            dst[0] = f2tf_f(rv.x); dst[1] = f2tf_f(rv.y);
            dst[2] = f2tf_f(rv.z); dst[3] = f2tf_f(rv.w);
        }
        float4 r1v[16];
        #pragma unroll
        for (int it = 0; it < 16; it++) {
            const int i = tid + it * 256;
            const int c = i >> 6, x = (i & 63) << 2;
            r1v[it] = *(const float4*)(outb + (size_t)(t * 64 + c) * DQ + e0g + 256 + x);
        }

        float acc1[4][4];
        #pragma unroll
        for (int n = 0; n < 4; n++) for (int q = 0; q < 4; q++) acc1[n][q] = 0.f;

        #pragma unroll
        for (int sec = 0; sec < 2; sec++) {
            if (sec == 1) {
                #pragma unroll
                for (int it = 0; it < 16; it++) {
                    const int i = tid + it * 256;
                    const int c = i >> 6, x = (i & 63) << 2;
                    float* dst = rs + c * RS_STRIDE + x;
                    dst[0] = f2tf_f(r1v[it].x); dst[1] = f2tf_f(r1v[it].y);
                    dst[2] = f2tf_f(r1v[it].z); dst[3] = f2tf_f(r1v[it].w);
                }
            }
            __syncthreads();

            if (t > 0) {
                for (int k = 0; k < 32; k++) {
                    uint32_t a[4];
                    a[0] = fu(rs[(wm + g    ) * RS_STRIDE + k * 8 + tg    ]);
                    a[1] = fu(rs[(wm + g + 8) * RS_STRIDE + k * 8 + tg    ]);
                    a[2] = fu(rs[(wm + g    ) * RS_STRIDE + k * 8 + tg + 4]);
                    a[3] = fu(rs[(wm + g + 8) * RS_STRIDE + k * 8 + tg + 4]);
                    #pragma unroll
                    for (int n = 0; n < 4; n++) {
                        const int d = (wn4 + n) * 8 + g;
                        uint32_t bb[2];
                        bb[0] = fu(Ws[d * WS_STRIDE + sec * 256 + k * 8 + tg    ]);
                        bb[1] = fu(Ws[d * WS_STRIDE + sec * 256 + k * 8 + tg + 4]);
                        mma8(acc1[n], a, bb);
                    }
                }
            }

            float acc2[2][8][4];
            #pragma unroll
            for (int m = 0; m < 2; m++) for (int n = 0; n < 8; n++) for (int q = 0; q < 4; q++) acc2[m][n][q] = 0.f;
            const float* prsec = prevrow + sec * 256;
            for (int kk = 0; kk < 8; kk++) {
                const int c0 = kk * 8 + tg - 1;
                const int c1 = kk * 8 + tg + 3;
                const float* r0 = (c0 >= 0) ? (rs + c0 * RS_STRIDE) : prsec;
                const float* r1 = rs + c1 * RS_STRIDE;
                uint32_t a[2][4], bb[8][2];
                #pragma unroll
                for (int m = 0; m < 2; m++) {
                    const int e = (wid * 2 + m) * 16;
                    a[m][0] = fu(r0[e + g    ]);
                    a[m][1] = fu(r0[e + g + 8]);
                    a[m][2] = fu(r1[e + g    ]);
                    a[m][3] = fu(r1[e + g + 8]);
                }
                #pragma unroll
                for (int n = 0; n < 8; n++) {
                    bb[n][0] = fu(us[(kk * 8 + tg    ) * US_STRIDE + n * 8 + g]);
                    bb[n][1] = fu(us[(kk * 8 + tg + 4) * US_STRIDE + n * 8 + g]);
                }
                #pragma unroll
                for (int m = 0; m < 2; m++)
                    #pragma unroll
                    for (int n = 0; n < 8; n++)
                        mma8(acc2[m][n], a[m], bb[n]);
            }
            __syncthreads();

            #pragma unroll
            for (int m = 0; m < 2; m++) {
                const int e = sec * 256 + (wid * 2 + m) * 16;
                #pragma unroll
                for (int n = 0; n < 8; n++) {
                    const int d = n * 8 + 2 * tg;
                    float* w00 = &Ws[(size_t)d       * WS_STRIDE + e + g];
                    float* w01 = &Ws[(size_t)(d + 1) * WS_STRIDE + e + g];
                    float* w10 = &Ws[(size_t)d       * WS_STRIDE + e + g + 8];
                    float* w11 = &Ws[(size_t)(d + 1) * WS_STRIDE + e + g + 8];
                    *w00 = fmaf(gC, *w00, acc2[m][n][0]);
                    *w01 = fmaf(gC, *w01, acc2[m][n][1]);
                    *w10 = fmaf(gC, *w10, acc2[m][n][2]);
                    *w11 = fmaf(gC, *w11, acc2[m][n][3]);
                }
            }
        }

        if (t > 0) {
            const int c0 = wm + g, c1 = wm + g + 8;
            #pragma unroll
            for (int n = 0; n < 4; n++) {
                const int dg = d0g + (wn4 + n) * 8 + 2 * tg;
                float2 v0 = make_float2(acc1[n][0] * s0, acc1[n][1] * s0);
                float2 v1 = make_float2(acc1[n][2] * s1, acc1[n][3] * s1);
                *(float2*)(pb + (size_t)(t * 64 + c0) * DQ + dg) = v0;
                *(float2*)(pb + (size_t)(t * 64 + c1) * DQ + dg) = v1;
            }
        } else {
            #pragma unroll
            for (int it = 0; it < 4; it++) {
                const int i = tid + it * 256;
                const int c = i >> 4, x = (i & 15) << 2;
                *(float4*)(pb + (size_t)c * DQ + d0g + x) = make_float4(0.f, 0.f, 0.f, 0.f);
            }
        }
        __syncthreads();
    }
}

// ---------------------------------------------------------------------------
extern "C" void kernel_launch(void* const* d_in, const int* in_sizes, int n_in,
                              void* d_out, int out_size)
{
    const float* out_in    = (const float*)d_in[0];
    const float* W_write   = (const float*)d_in[1];
    const float* W_read    = (const float*)d_in[2];
    const float* decay     = (const float*)d_in[3];
    const float* log_alpha = (const float*)d_in[4];
    float* outp = (float*)d_out;

    static bool init_done = false;
    static cudaStream_t s2 = nullptr;
    static cudaEvent_t ev1 = nullptr, ev2 = nullptr;
    if (!init_done) {
        cudaFuncSetAttribute(scan_kernel, cudaFuncAttributeMaxDynamicSharedMemorySize, SCAN_SMEM);
        cudaStreamCreateWithFlags(&s2, cudaStreamNonBlocking);
        cudaEventCreateWithFlags(&ev1, cudaEventDisableTiming);
        cudaEventCreateWithFlags(&ev2, cudaEventDisableTiming);
        init_done = true;
    }

    void *pv = nullptr, *pr = nullptr, *pp0 = nullptr, *pp1 = nullptr;
    void *pah = nullptr, *pbh = nullptr, *pbh2 = nullptr;
    cudaGetSymbolAddress(&pv, g_v);
    cudaGetSymbolAddress(&pr, g_reads);
    cudaGetSymbolAddress(&pp0, g_p0);
    cudaGetSymbolAddress(&pp1, g_p1);
    cudaGetSymbolAddress(&pah, g_Ah);
    cudaGetSymbolAddress(&pbh, g_Bh);
    cudaGetSymbolAddress(&pbh2, g_Bh2);
    uint32_t* Ah = (uint32_t*)pah;
    uint32_t* Bh = (uint32_t*)pbh;
    uint32_t* Bh2 = (uint32_t*)pbh2;

    dim3 ggemm(DQ / 128, MQ / 128);  // (8, 256)

    // prep: conv both weight matrices (independent) and out
    conv_frag_b<<<dim3(DQ / 128, 64), 256>>>(W_write, Bh);
    conv_frag_b<<<dim3(DQ / 128, 64), 256>>>(W_read, Bh2);
    conv_frag_a<<<dim3(MQ / 128, 64), 256>>>(out_in, nullptr, nullptr, Ah);

    // GEMM1: v = out @ W_write^T
    gemm_h<<<ggemm, 256>>>(Ah, Bh, nullptr, (float*)pv, nullptr);

    // fork: scan on s2, intra on main stream (independent of each other)
    cudaEventRecord(ev1, 0);
    cudaStreamWaitEvent(s2, ev1, 0);
    scan_kernel<<<dim3(16, 2, BQ), 256, SCAN_SMEM, s2>>>(out_in, decay, (float*)pp0, (float*)pp1);
    cudaEventRecord(ev2, s2);

    intra_kernel<<<dim3(NCQ, BQ), 256>>>(out_in, decay);

    // join: main stream waits for scan before consuming g_p0/g_p1
    cudaStreamWaitEvent(0, ev2, 0);

    // GEMM2 prep + GEMM2: output = out + alpha*((g_reads+g_p0+g_p1) @ W_read^T)
    conv_frag_a<<<dim3(MQ / 128, 64), 256>>>((const float*)pr, (const float*)pp0, (const float*)pp1, Ah);
    gemm_h<<<ggemm, 256>>>(Ah, Bh2, out_in, outp, log_alpha);
}